// round 5
// baseline (speedup 1.0000x reference)
#include <cuda_runtime.h>
#include <cuda_bf16.h>
#include <cstdint>
#include <cstddef>

// Problem constants
#define BB 2
#define CC 256
#define HH 64
#define WW 64
#define PP 4096          // H*W
#define NSET 128
#define GG 64            // groups
#define CGC 4            // channels per group

// ---------------- scratch (device globals; no allocs allowed) ----------------
__device__ float g_mean[BB * CC];
__device__ float g_sca[BB * CC];
__device__ float g_ydw1[BB * CC * PP];
__device__ float g_yc1a[BB * CC * PP];
__device__ float g_attlin[BB * NSET * PP];
__device__ float g_x1[BB * CC * PP];
__device__ float g_uf[BB * CC * PP];
__device__ float g_l0[BB * CC * PP];
__device__ float g_l1[BB * CC * PP];
__device__ float g_tg[BB * 16 * PP];
__device__ float g_att[BB * NSET * PP];
__device__ float g_x2[BB * CC * PP];
__device__ float g_z[BB * CC * PP];

__device__ __forceinline__ uint32_t f2tf(float f) {
    uint32_t r;
    asm("cvt.rna.tf32.f32 %0, %1;" : "=r"(r) : "f"(f));
    return r;
}

// ---------------- mean over H,W per (b,c) ----------------
__global__ void __launch_bounds__(256) meankern(const float* __restrict__ X,
                                                float* __restrict__ M) {
    int bc = blockIdx.x;
    const float4* xp = (const float4*)(X + (size_t)bc * PP);
    float s = 0.f;
    for (int p = threadIdx.x; p < PP / 4; p += 256) {
        float4 v = xp[p];
        s += v.x + v.y + v.z + v.w;
    }
    __shared__ float red[256];
    red[threadIdx.x] = s;
    __syncthreads();
    for (int st = 128; st > 0; st >>= 1) {
        if (threadIdx.x < st) red[threadIdx.x] += red[threadIdx.x + st];
        __syncthreads();
    }
    if (threadIdx.x == 0) M[bc] = red[0] * (1.f / PP);
}

// ---------------- sca = 1x1 conv on the mean vector ----------------
__global__ void __launch_bounds__(256) scakern(const float* __restrict__ M,
                                               const float* __restrict__ Wsca,
                                               const float* __restrict__ Bsca,
                                               float* __restrict__ SCA) {
    int b = blockIdx.x;
    int o = threadIdx.x;
    __shared__ float m[CC];
    m[o] = M[b * CC + o];
    __syncthreads();
    float s = Bsca[o];
    const float* wr = Wsca + (size_t)o * CC;
    for (int c = 0; c < CC; c++) s += wr[c] * m[c];
    SCA[b * CC + o] = s;
}

// ---------------- core 64x64 SIMT GEMM body (device inline) ----------------
__device__ __forceinline__ void gemm_core(const float* __restrict__ Wm,
                                          const float* __restrict__ Xb,
                                          int m0, int n0, int K,
                                          float (&acc)[4][4]) {
    __shared__ float As[16][68];
    __shared__ float Bs[16][64];
    int tid = threadIdx.x;
    int tx = tid & 15, ty = tid >> 4;
    int arow = tid >> 2, ak = (tid & 3) << 2;
    int brow = tid >> 4, bn = (tid & 15) << 2;
    for (int k0 = 0; k0 < K; k0 += 16) {
        float4 av = *(const float4*)&Wm[(size_t)(m0 + arow) * K + k0 + ak];
        As[ak + 0][arow] = av.x;
        As[ak + 1][arow] = av.y;
        As[ak + 2][arow] = av.z;
        As[ak + 3][arow] = av.w;
        *(float4*)&Bs[brow][bn] =
            *(const float4*)&Xb[(size_t)(k0 + brow) * PP + n0 + bn];
        __syncthreads();
#pragma unroll
        for (int k = 0; k < 16; k++) {
            float4 a = *(const float4*)&As[k][ty << 2];
            float4 bq = *(const float4*)&Bs[k][tx << 2];
            acc[0][0] += a.x * bq.x; acc[0][1] += a.x * bq.y;
            acc[0][2] += a.x * bq.z; acc[0][3] += a.x * bq.w;
            acc[1][0] += a.y * bq.x; acc[1][1] += a.y * bq.y;
            acc[1][2] += a.y * bq.z; acc[1][3] += a.y * bq.w;
            acc[2][0] += a.z * bq.x; acc[2][1] += a.z * bq.y;
            acc[2][2] += a.z * bq.z; acc[2][3] += a.z * bq.w;
            acc[3][0] += a.w * bq.x; acc[3][1] += a.w * bq.y;
            acc[3][2] += a.w * bq.z; acc[3][3] += a.w * bq.w;
        }
        __syncthreads();
    }
}

// ---------------- plain 1x1 GEMM (proj) ----------------
__global__ void __launch_bounds__(256) gemm1x1(const float* __restrict__ Wm,
                                               const float* __restrict__ X,
                                               const float* __restrict__ bias,
                                               float* __restrict__ Y,
                                               int M, int K) {
    int b = blockIdx.z;
    int m0 = blockIdx.y << 6, n0 = blockIdx.x << 6;
    float acc[4][4] = {};
    gemm_core(Wm, X + (size_t)b * K * PP, m0, n0, K, acc);
    int tid = threadIdx.x, tx = tid & 15, ty = tid >> 4;
    float* Yb = Y + (size_t)b * M * PP;
#pragma unroll
    for (int i = 0; i < 4; i++) {
        int m = m0 + (ty << 2) + i;
        float bb = bias ? bias[m] : 0.f;
        float4 o = make_float4(acc[i][0] + bb, acc[i][1] + bb,
                               acc[i][2] + bb, acc[i][3] + bb);
        *(float4*)&Yb[(size_t)m * PP + n0 + (tx << 2)] = o;
    }
}

// ---------------- batched 3-way 1x1 GEMM (dw1 | c1a | c211) ----------------
__global__ void __launch_bounds__(256) gemm3(const float* __restrict__ W0,
                                             const float* __restrict__ W1,
                                             const float* __restrict__ W2,
                                             const float* __restrict__ b2,
                                             const float* __restrict__ X,
                                             float* __restrict__ Y0,
                                             float* __restrict__ Y1,
                                             float* __restrict__ Y2) {
    int b = blockIdx.z;
    int my = blockIdx.y, n0 = blockIdx.x << 6;
    const float* Wm;
    float* Y;
    const float* bias = nullptr;
    int m0, Msel;
    if (my < 4)      { Wm = W0; Y = Y0; m0 = my << 6; Msel = 256; }
    else if (my < 8) { Wm = W1; Y = Y1; m0 = (my - 4) << 6; Msel = 256; }
    else             { Wm = W2; Y = Y2; m0 = (my - 8) << 6; Msel = 128; bias = b2; }
    float acc[4][4] = {};
    gemm_core(Wm, X + (size_t)b * CC * PP, m0, n0, CC, acc);
    int tid = threadIdx.x, tx = tid & 15, ty = tid >> 4;
    float* Yb = Y + (size_t)b * Msel * PP;
#pragma unroll
    for (int i = 0; i < 4; i++) {
        int m = m0 + (ty << 2) + i;
        float bb = bias ? bias[m] : 0.f;
        float4 o = make_float4(acc[i][0] + bb, acc[i][1] + bb,
                               acc[i][2] + bb, acc[i][3] + bb);
        *(float4*)&Yb[(size_t)m * PP + n0 + (tx << 2)] = o;
    }
}

// ---------------- lka1 GEMM with fused z = lka*x1*x2*sca epilogue ----------------
__global__ void __launch_bounds__(256) gemm_lka_ew(const float* __restrict__ Wm,
                                                   const float* __restrict__ X,
                                                   const float* __restrict__ bias,
                                                   const float* __restrict__ X1,
                                                   const float* __restrict__ X2,
                                                   const float* __restrict__ SCA,
                                                   float* __restrict__ Z) {
    int b = blockIdx.z;
    int m0 = blockIdx.y << 6, n0 = blockIdx.x << 6;
    float acc[4][4] = {};
    gemm_core(Wm, X + (size_t)b * CC * PP, m0, n0, CC, acc);
    int tid = threadIdx.x, tx = tid & 15, ty = tid >> 4;
    size_t bbase = (size_t)b * CC * PP;
#pragma unroll
    for (int i = 0; i < 4; i++) {
        int m = m0 + (ty << 2) + i;
        float bb = bias[m];
        float sc = SCA[b * CC + m];
        size_t idx = bbase + (size_t)m * PP + n0 + (tx << 2);
        float4 v1 = *(const float4*)&X1[idx];
        float4 v2 = *(const float4*)&X2[idx];
        float4 o = make_float4((acc[i][0] + bb) * v1.x * v2.x * sc,
                               (acc[i][1] + bb) * v1.y * v2.y * sc,
                               (acc[i][2] + bb) * v1.z * v2.z * sc,
                               (acc[i][3] + bb) * v1.w * v2.w * sc);
        *(float4*)&Z[idx] = o;
    }
}

// ---------------- depthwise conv body ----------------
template <int KS, int DIL, int PAD>
__device__ __forceinline__ void dw_body(const float* __restrict__ xp,
                                        const float* __restrict__ wrow,
                                        float* __restrict__ yp) {
    __shared__ float tile[PP];
    __shared__ float w[KS * KS];
    for (int p = threadIdx.x; p < PP / 4; p += 256)
        ((float4*)tile)[p] = ((const float4*)xp)[p];
    if (threadIdx.x < KS * KS) w[threadIdx.x] = wrow[threadIdx.x];
    __syncthreads();
    for (int p = threadIdx.x; p < PP; p += 256) {
        int h = p >> 6, ww = p & 63;
        float s = 0.f;
#pragma unroll
        for (int kh = 0; kh < KS; kh++) {
            int hh = h + DIL * kh - PAD;
            if ((unsigned)hh >= (unsigned)HH) continue;
#pragma unroll
            for (int kw = 0; kw < KS; kw++) {
                int wc = ww + DIL * kw - PAD;
                if ((unsigned)wc >= (unsigned)WW) continue;
                s += tile[hh * WW + wc] * w[kh * KS + kw];
            }
        }
        yp[p] = s;
    }
}

template <int KS, int DIL, int PAD>
__global__ void __launch_bounds__(256) dwconv(const float* __restrict__ X,
                                              const float* __restrict__ Wd,
                                              float* __restrict__ Y) {
    int bc = blockIdx.x;
    int c = bc & (CC - 1);
    dw_body<KS, DIL, PAD>(X + (size_t)bc * PP, Wd + c * KS * KS,
                          Y + (size_t)bc * PP);
}

// two independent 3x3 depthwise convs in one launch
__global__ void __launch_bounds__(256) dw3x3_pair(const float* __restrict__ X0,
                                                  const float* __restrict__ W0,
                                                  float* __restrict__ Y0,
                                                  const float* __restrict__ X1,
                                                  const float* __restrict__ W1,
                                                  float* __restrict__ Y1) {
    int id = blockIdx.x;
    int which = id >> 9, bc = id & 511;
    int c = bc & (CC - 1);
    const float* X = which ? X1 : X0;
    const float* W = which ? W1 : W0;
    float* Y = which ? Y1 : Y0;
    dw_body<3, 1, 1>(X + (size_t)bc * PP, W + c * 9, Y + (size_t)bc * PP);
}

// ---------------- c2a grouped conv (groups=32) + SimpleGate ----------------
__global__ void __launch_bounds__(256) c2a_gate(const float* __restrict__ X,
                                                const float* __restrict__ Wg,
                                                const float* __restrict__ bg,
                                                float* __restrict__ TG) {
    int b = blockIdx.x >> 4, j = blockIdx.x & 15;
    int p0 = blockIdx.y * 512;
    __shared__ float w1[72], w2[72];
    if (threadIdx.x < 72) w1[threadIdx.x] = Wg[j * 72 + threadIdx.x];
    else if (threadIdx.x < 144) w2[threadIdx.x - 72] = Wg[(16 + j) * 72 + threadIdx.x - 72];
    __syncthreads();
    float b1 = bg[j], b2 = bg[16 + j];
    const float* x1p = X + ((size_t)b * CC + j * 8) * PP;
    const float* x2p = X + ((size_t)b * CC + (16 + j) * 8) * PP;
    for (int p = p0 + threadIdx.x; p < p0 + 512; p += 256) {
        int h = p >> 6, wq = p & 63;
        float t1 = b1, t2 = b2;
        for (int ci = 0; ci < 8; ci++) {
#pragma unroll
            for (int kh = 0; kh < 3; kh++) {
                int hh = h + kh - 1;
                if ((unsigned)hh >= (unsigned)HH) continue;
#pragma unroll
                for (int kw = 0; kw < 3; kw++) {
                    int wc = wq + kw - 1;
                    if ((unsigned)wc >= (unsigned)WW) continue;
                    float xv1 = x1p[(size_t)ci * PP + hh * WW + wc];
                    float xv2 = x2p[(size_t)ci * PP + hh * WW + wc];
                    t1 += xv1 * w1[ci * 9 + kh * 3 + kw];
                    t2 += xv2 * w2[ci * 9 + kh * 3 + kw];
                }
            }
        }
        TG[((size_t)b * 16 + j) * PP + p] = t1 * t2;
    }
}

// ---------------- att = (conv1x1(tg,c2b)+b)*gamma + attlin ----------------
__global__ void __launch_bounds__(256) att_mix(const float* __restrict__ TG,
                                               const float* __restrict__ c2bw,
                                               const float* __restrict__ c2bb,
                                               const float* __restrict__ attg,
                                               const float* __restrict__ ATTLIN,
                                               float* __restrict__ ATT) {
    int n = blockIdx.x;
    int b = blockIdx.z;
    int p0 = blockIdx.y * 1024;
    float wr[16];
#pragma unroll
    for (int q = 0; q < 16; q++) wr[q] = c2bw[n * 16 + q];
    float bb = c2bb[n], gam = attg[n];
    const float* tgb = TG + (size_t)b * 16 * PP;
    size_t base = ((size_t)b * NSET + n) * PP;
    for (int p = p0 + threadIdx.x; p < p0 + 1024; p += 256) {
        float s = bb;
#pragma unroll
        for (int q = 0; q < 16; q++) s += tgb[(size_t)q * PP + p] * wr[q];
        ATT[base + p] = s * gam + ATTLIN[base + p];
    }
}

// =========================================================================
// Fused IKBA: both passes + 2 groups per block, tf32 mma.sync (m16n8k8).
// Block = (gpair in 0..31, h2 in 0..31, b). 256 threads = 8 warps.
// A [128 pixels x 128 k] stride 133.
// B [208 rows x 128 k] stride 133:
//   n 0..95   : vertical w_cb cols gpair*96 + n
//   n 96..103 : zero
//   n 104..207: per group grp = (n-104)/52, r = (n-104)%52:
//               r<48 -> horizontal w_cb col gpair*96 + grp*48 + r
//               else -> b_cb channel gpair*8 + grp*4 + (r-48)
// GEMM 128x208x128: warp (wm 0..3, wn 0..1): rows 32*wm.., cols 104*wn..
// Epilogue: C -> smem [128][210]; vertical matvec (uf global) -> xh smem;
// horizontal matvec (xh smem, row-internal taps) + bias; out = s*ga1 + UFR.
// =========================================================================
#define AS_F (128 * 133)
#define BS_F (208 * 133)
#define XH_OFF (AS_F + BS_F)
#define IKBA_F (XH_OFF + 8 * 128)
#define CS_STRIDE 210

__global__ void __launch_bounds__(256) ikba_fused(const float* __restrict__ ATT,
                                                  const float* __restrict__ wcb,
                                                  const float* __restrict__ bcb,
                                                  const float* __restrict__ ga1,
                                                  const float* __restrict__ UF,
                                                  float* __restrict__ OUT) {
    extern __shared__ float sm[];
    uint32_t* Asu = (uint32_t*)sm;            // [128][133]
    uint32_t* Bsu = (uint32_t*)(sm + AS_F);   // [208][133]
    float* Cs = sm;                            // alias after GEMM: [128][210]
    float* xh = sm + XH_OFF;                   // [8][128]

    int gpair = blockIdx.x, h2 = blockIdx.y, b = blockIdx.z;
    int tid = threadIdx.x;

    // ---- A fill: thread (pix = tid&127, half = tid>>7) covers 64 k's
    {
        int pix = tid & 127, half = tid >> 7;
        const float* ap = ATT + (size_t)b * NSET * PP + (size_t)h2 * 128 + pix;
        int k0 = half * 64;
#pragma unroll 4
        for (int k = k0; k < k0 + 64; k++)
            Asu[pix * 133 + k] = f2tf(ap[(size_t)k * PP]);
    }
    // ---- B fill
    for (int l = tid; l < 208 * 128; l += 256) {
        int k = l / 208, n = l - k * 208;
        float v = 0.f;
        if (n < 96) {
            v = wcb[(size_t)k * 6144 + gpair * 96 + n];
        } else if (n >= 104) {
            int m = n - 104, grp = m / 52, r = m - grp * 52;
            if (r < 48) v = wcb[3072 + (size_t)k * 6144 + gpair * 96 + grp * 48 + r];
            else        v = bcb[k * CC + gpair * 8 + grp * 4 + (r - 48)];
        }
        Bsu[n * 133 + k] = f2tf(v);
    }
    __syncthreads();

    // ---- GEMM
    int warp = tid >> 5, lane = tid & 31;
    int wm = warp & 3, wn = warp >> 2;
    int qr = lane >> 2, l4 = lane & 3;
    int m_base = wm << 5;
    int n_base = wn * 104;
    float acc[2][13][4];
#pragma unroll
    for (int i = 0; i < 2; i++)
#pragma unroll
        for (int j = 0; j < 13; j++)
#pragma unroll
            for (int t = 0; t < 4; t++) acc[i][j][t] = 0.f;

    for (int k0 = 0; k0 < 128; k0 += 8) {
        uint32_t a[2][4];
#pragma unroll
        for (int mt = 0; mt < 2; mt++) {
            int base = (m_base + mt * 16 + qr) * 133 + k0 + l4;
            a[mt][0] = Asu[base];
            a[mt][1] = Asu[base + 8 * 133];
            a[mt][2] = Asu[base + 4];
            a[mt][3] = Asu[base + 8 * 133 + 4];
        }
#pragma unroll
        for (int nt = 0; nt < 13; nt++) {
            int nr = (n_base + nt * 8 + qr) * 133 + k0 + l4;
            uint32_t b0 = Bsu[nr];
            uint32_t b1 = Bsu[nr + 4];
#pragma unroll
            for (int mt = 0; mt < 2; mt++) {
                asm volatile(
                    "mma.sync.aligned.m16n8k8.row.col.f32.tf32.tf32.f32 "
                    "{%0,%1,%2,%3}, {%4,%5,%6,%7}, {%8,%9}, {%0,%1,%2,%3};"
                    : "+f"(acc[mt][nt][0]), "+f"(acc[mt][nt][1]),
                      "+f"(acc[mt][nt][2]), "+f"(acc[mt][nt][3])
                    : "r"(a[mt][0]), "r"(a[mt][1]), "r"(a[mt][2]), "r"(a[mt][3]),
                      "r"(b0), "r"(b1));
            }
        }
    }
    __syncthreads();   // all A/B reads complete before alias overwrite

    // ---- store C tile
#pragma unroll
    for (int mt = 0; mt < 2; mt++)
#pragma unroll
        for (int nt = 0; nt < 13; nt++) {
            int r = m_base + mt * 16 + qr;
            int cl = n_base + nt * 8 + 2 * l4;
            *(float2*)&Cs[r * CS_STRIDE + cl] =
                make_float2(acc[mt][nt][0], acc[mt][nt][1]);
            *(float2*)&Cs[(r + 8) * CS_STRIDE + cl] =
                make_float2(acc[mt][nt][2], acc[mt][nt][3]);
        }
    __syncthreads();

    // ---- vertical matvec: thread (pix, grp) -> xh[grp*4+oi][pix]
    int pix = tid & 127, grp = tid >> 7;
    int r0 = pix >> 6, cp = pix & 63;
    int h = h2 * 2 + r0;
    {
        float uf[12];
        size_t srcBase = (size_t)(b * CC + gpair * 8 + grp * 4) * PP;
#pragma unroll
        for (int ci = 0; ci < 4; ci++)
#pragma unroll
            for (int tap = 0; tap < 3; tap++) {
                float v = 0.f;
                int hh = h + tap - 1;
                if ((unsigned)hh < (unsigned)HH)
                    v = UF[srcBase + (size_t)ci * PP + hh * WW + cp];
                uf[ci * 3 + tap] = v;
            }
        const float* cv = &Cs[pix * CS_STRIDE + grp * 48];
#pragma unroll
        for (int oi = 0; oi < 4; oi++) {
            float s = 0.f;
#pragma unroll
            for (int j = 0; j < 12; j++) s += cv[oi * 12 + j] * uf[j];
            xh[(grp * 4 + oi) * 128 + pix] = s;
        }
    }
    __syncthreads();

    // ---- horizontal matvec + bias, out = s*ga1 + UF
    {
        float ufh[12];
#pragma unroll
        for (int ci = 0; ci < 4; ci++)
#pragma unroll
            for (int tap = 0; tap < 3; tap++) {
                float v = 0.f;
                int wc = cp + tap - 1;
                if ((unsigned)wc < (unsigned)WW)
                    v = xh[(grp * 4 + ci) * 128 + (pix + tap - 1)];
                ufh[ci * 3 + tap] = v;
            }
        const float* ch = &Cs[pix * CS_STRIDE + 104 + grp * 52];
        size_t obase = (size_t)(b * CC + gpair * 8 + grp * 4) * PP
                     + (size_t)h2 * 128 + pix;
#pragma unroll
        for (int oi = 0; oi < 4; oi++) {
            float s = ch[48 + oi];
#pragma unroll
            for (int j = 0; j < 12; j++) s += ch[oi * 12 + j] * ufh[j];
            size_t oidx = obase + (size_t)oi * PP;
            OUT[oidx] = s * ga1[gpair * 8 + grp * 4 + oi] + UF[oidx];
        }
    }
}

// ---------------- launch ----------------
extern "C" void kernel_launch(void* const* d_in, const int* in_sizes, int n_in,
                              void* d_out, int out_size) {
    const float* x       = (const float*)d_in[0];
    const float* dw1_w   = (const float*)d_in[1];
    const float* dw2_w   = (const float*)d_in[2];
    const float* proj_w  = (const float*)d_in[3];
    const float* lka0_w  = (const float*)d_in[4];
    const float* lkas_w  = (const float*)d_in[5];
    const float* lka1_w  = (const float*)d_in[6];
    const float* lka1_b  = (const float*)d_in[7];
    const float* sca_w   = (const float*)d_in[8];
    const float* sca_b   = (const float*)d_in[9];
    const float* c1a_w   = (const float*)d_in[10];
    const float* c1b_w   = (const float*)d_in[11];
    const float* c2a_w   = (const float*)d_in[12];
    const float* c2a_b   = (const float*)d_in[13];
    const float* c2b_w   = (const float*)d_in[14];
    const float* c2b_b   = (const float*)d_in[15];
    const float* c211_w  = (const float*)d_in[16];
    const float* c211_b  = (const float*)d_in[17];
    const float* w_cb    = (const float*)d_in[18];
    const float* b_cb    = (const float*)d_in[19];
    const float* attgam  = (const float*)d_in[20];
    const float* ga1     = (const float*)d_in[21];
    float* out = (float*)d_out;

    float *meanb, *scab, *ydw1, *yc1a, *attlin, *x1b, *ufb, *l0, *l1,
          *tg, *att, *x2b, *zb;
    cudaGetSymbolAddress((void**)&meanb, g_mean);
    cudaGetSymbolAddress((void**)&scab, g_sca);
    cudaGetSymbolAddress((void**)&ydw1, g_ydw1);
    cudaGetSymbolAddress((void**)&yc1a, g_yc1a);
    cudaGetSymbolAddress((void**)&attlin, g_attlin);
    cudaGetSymbolAddress((void**)&x1b, g_x1);
    cudaGetSymbolAddress((void**)&ufb, g_uf);
    cudaGetSymbolAddress((void**)&l0, g_l0);
    cudaGetSymbolAddress((void**)&l1, g_l1);
    cudaGetSymbolAddress((void**)&tg, g_tg);
    cudaGetSymbolAddress((void**)&att, g_att);
    cudaGetSymbolAddress((void**)&x2b, g_x2);
    cudaGetSymbolAddress((void**)&zb, g_z);

    // channel-attention branch
    meankern<<<BB * CC, 256>>>(x, meanb);
    scakern<<<BB, 256>>>(meanb, sca_w, sca_b, scab);

    // 1x1 convs from x, batched (dw1 -> ydw1, c1a -> yc1a, c211 -> attlin)
    gemm3<<<dim3(64, 10, BB), 256>>>(dw1_w, c1a_w, c211_w, c211_b, x,
                                     ydw1, yc1a, attlin);

    // depthwise chains (two 3x3 merged into one launch)
    dw3x3_pair<<<BB * CC * 2, 256>>>(ydw1, dw2_w, x1b, yc1a, c1b_w, ufb);
    dwconv<5, 1, 2><<<BB * CC, 256>>>(x, lka0_w, l0);
    dwconv<7, 3, 9><<<BB * CC, 256>>>(l0, lkas_w, l1);

    // attention map
    c2a_gate<<<dim3(BB * 16, 8), 256>>>(x, c2a_w, c2a_b, tg);
    att_mix<<<dim3(NSET, 4, BB), 256>>>(tg, c2b_w, c2b_b, attgam, attlin, att);

    // fused IKBA (both passes, 2 groups per block)
    size_t shmem = IKBA_F * sizeof(float);
    cudaFuncSetAttribute(ikba_fused, cudaFuncAttributeMaxDynamicSharedMemorySize,
                         (int)shmem);
    ikba_fused<<<dim3(32, 32, BB), 256, shmem>>>(att, w_cb, b_cb, ga1, ufb, x2b);

    // lka1 GEMM with fused elementwise merge: z = (W@l1+b)*x1*x2*sca
    gemm_lka_ew<<<dim3(64, 4, BB), 256>>>(lka1_w, l1, lka1_b, x1b, x2b, scab, zb);

    // final projection
    gemm1x1<<<dim3(64, 4, BB), 256>>>(proj_w, zb, nullptr, out, 256, 256);
}

// round 6
// speedup vs baseline: 1.7745x; 1.7745x over previous
#include <cuda_runtime.h>
#include <cuda_bf16.h>
#include <cstdint>
#include <cstddef>

// Problem constants
#define BB 2
#define CC 256
#define HH 64
#define WW 64
#define PP 4096          // H*W
#define NSET 128
#define GG 64            // groups
#define CGC 4            // channels per group

// ---------------- scratch (device globals; no allocs allowed) ----------------
__device__ float g_mean[BB * CC];
__device__ float g_sca[BB * CC];
__device__ float g_ydw1[BB * CC * PP];
__device__ float g_yc1a[BB * CC * PP];
__device__ float g_attlin[BB * NSET * PP];
__device__ float g_x1[BB * CC * PP];
__device__ float g_uf[BB * CC * PP];
__device__ float g_l0[BB * CC * PP];
__device__ float g_l1[BB * CC * PP];
__device__ float g_tg[BB * 16 * PP];
__device__ float g_att[BB * NSET * PP];
__device__ float g_xh[BB * CC * PP];
__device__ float g_x2[BB * CC * PP];
__device__ float g_z[BB * CC * PP];

__device__ __forceinline__ uint32_t f2tf(float f) {
    uint32_t r;
    asm("cvt.rna.tf32.f32 %0, %1;" : "=r"(r) : "f"(f));
    return r;
}

// ---------------- mean over H,W per (b,c) ----------------
__global__ void __launch_bounds__(256) meankern(const float* __restrict__ X,
                                                float* __restrict__ M) {
    int bc = blockIdx.x;
    const float4* xp = (const float4*)(X + (size_t)bc * PP);
    float s = 0.f;
    for (int p = threadIdx.x; p < PP / 4; p += 256) {
        float4 v = xp[p];
        s += v.x + v.y + v.z + v.w;
    }
    __shared__ float red[256];
    red[threadIdx.x] = s;
    __syncthreads();
    for (int st = 128; st > 0; st >>= 1) {
        if (threadIdx.x < st) red[threadIdx.x] += red[threadIdx.x + st];
        __syncthreads();
    }
    if (threadIdx.x == 0) M[bc] = red[0] * (1.f / PP);
}

// ---------------- sca = 1x1 conv on the mean vector ----------------
__global__ void __launch_bounds__(256) scakern(const float* __restrict__ M,
                                               const float* __restrict__ Wsca,
                                               const float* __restrict__ Bsca,
                                               float* __restrict__ SCA) {
    int b = blockIdx.x;
    int o = threadIdx.x;
    __shared__ float m[CC];
    m[o] = M[b * CC + o];
    __syncthreads();
    float s = Bsca[o];
    const float* wr = Wsca + (size_t)o * CC;
    for (int c = 0; c < CC; c++) s += wr[c] * m[c];
    SCA[b * CC + o] = s;
}

// ---------------- core 64x64 SIMT GEMM body (device inline) ----------------
__device__ __forceinline__ void gemm_core(const float* __restrict__ Wm,
                                          const float* __restrict__ Xb,
                                          int m0, int n0, int K,
                                          float (&acc)[4][4]) {
    __shared__ float As[16][68];
    __shared__ float Bs[16][64];
    int tid = threadIdx.x;
    int tx = tid & 15, ty = tid >> 4;
    int arow = tid >> 2, ak = (tid & 3) << 2;
    int brow = tid >> 4, bn = (tid & 15) << 2;
    for (int k0 = 0; k0 < K; k0 += 16) {
        float4 av = *(const float4*)&Wm[(size_t)(m0 + arow) * K + k0 + ak];
        As[ak + 0][arow] = av.x;
        As[ak + 1][arow] = av.y;
        As[ak + 2][arow] = av.z;
        As[ak + 3][arow] = av.w;
        *(float4*)&Bs[brow][bn] =
            *(const float4*)&Xb[(size_t)(k0 + brow) * PP + n0 + bn];
        __syncthreads();
#pragma unroll
        for (int k = 0; k < 16; k++) {
            float4 a = *(const float4*)&As[k][ty << 2];
            float4 bq = *(const float4*)&Bs[k][tx << 2];
            acc[0][0] += a.x * bq.x; acc[0][1] += a.x * bq.y;
            acc[0][2] += a.x * bq.z; acc[0][3] += a.x * bq.w;
            acc[1][0] += a.y * bq.x; acc[1][1] += a.y * bq.y;
            acc[1][2] += a.y * bq.z; acc[1][3] += a.y * bq.w;
            acc[2][0] += a.z * bq.x; acc[2][1] += a.z * bq.y;
            acc[2][2] += a.z * bq.z; acc[2][3] += a.z * bq.w;
            acc[3][0] += a.w * bq.x; acc[3][1] += a.w * bq.y;
            acc[3][2] += a.w * bq.z; acc[3][3] += a.w * bq.w;
        }
        __syncthreads();
    }
}

// ---------------- plain 1x1 GEMM (proj) ----------------
__global__ void __launch_bounds__(256) gemm1x1(const float* __restrict__ Wm,
                                               const float* __restrict__ X,
                                               const float* __restrict__ bias,
                                               float* __restrict__ Y,
                                               int M, int K) {
    int b = blockIdx.z;
    int m0 = blockIdx.y << 6, n0 = blockIdx.x << 6;
    float acc[4][4] = {};
    gemm_core(Wm, X + (size_t)b * K * PP, m0, n0, K, acc);
    int tid = threadIdx.x, tx = tid & 15, ty = tid >> 4;
    float* Yb = Y + (size_t)b * M * PP;
#pragma unroll
    for (int i = 0; i < 4; i++) {
        int m = m0 + (ty << 2) + i;
        float bb = bias ? bias[m] : 0.f;
        float4 o = make_float4(acc[i][0] + bb, acc[i][1] + bb,
                               acc[i][2] + bb, acc[i][3] + bb);
        *(float4*)&Yb[(size_t)m * PP + n0 + (tx << 2)] = o;
    }
}

// ---------------- batched 3-way 1x1 GEMM (dw1 | c1a | c211) ----------------
__global__ void __launch_bounds__(256) gemm3(const float* __restrict__ W0,
                                             const float* __restrict__ W1,
                                             const float* __restrict__ W2,
                                             const float* __restrict__ b2,
                                             const float* __restrict__ X,
                                             float* __restrict__ Y0,
                                             float* __restrict__ Y1,
                                             float* __restrict__ Y2) {
    int b = blockIdx.z;
    int my = blockIdx.y, n0 = blockIdx.x << 6;
    const float* Wm;
    float* Y;
    const float* bias = nullptr;
    int m0, Msel;
    if (my < 4)      { Wm = W0; Y = Y0; m0 = my << 6; Msel = 256; }
    else if (my < 8) { Wm = W1; Y = Y1; m0 = (my - 4) << 6; Msel = 256; }
    else             { Wm = W2; Y = Y2; m0 = (my - 8) << 6; Msel = 128; bias = b2; }
    float acc[4][4] = {};
    gemm_core(Wm, X + (size_t)b * CC * PP, m0, n0, CC, acc);
    int tid = threadIdx.x, tx = tid & 15, ty = tid >> 4;
    float* Yb = Y + (size_t)b * Msel * PP;
#pragma unroll
    for (int i = 0; i < 4; i++) {
        int m = m0 + (ty << 2) + i;
        float bb = bias ? bias[m] : 0.f;
        float4 o = make_float4(acc[i][0] + bb, acc[i][1] + bb,
                               acc[i][2] + bb, acc[i][3] + bb);
        *(float4*)&Yb[(size_t)m * PP + n0 + (tx << 2)] = o;
    }
}

// ---------------- lka1 GEMM with fused z = lka*x1*x2*sca epilogue ----------------
__global__ void __launch_bounds__(256) gemm_lka_ew(const float* __restrict__ Wm,
                                                   const float* __restrict__ X,
                                                   const float* __restrict__ bias,
                                                   const float* __restrict__ X1,
                                                   const float* __restrict__ X2,
                                                   const float* __restrict__ SCA,
                                                   float* __restrict__ Z) {
    int b = blockIdx.z;
    int m0 = blockIdx.y << 6, n0 = blockIdx.x << 6;
    float acc[4][4] = {};
    gemm_core(Wm, X + (size_t)b * CC * PP, m0, n0, CC, acc);
    int tid = threadIdx.x, tx = tid & 15, ty = tid >> 4;
    size_t bbase = (size_t)b * CC * PP;
#pragma unroll
    for (int i = 0; i < 4; i++) {
        int m = m0 + (ty << 2) + i;
        float bb = bias[m];
        float sc = SCA[b * CC + m];
        size_t idx = bbase + (size_t)m * PP + n0 + (tx << 2);
        float4 v1 = *(const float4*)&X1[idx];
        float4 v2 = *(const float4*)&X2[idx];
        float4 o = make_float4((acc[i][0] + bb) * v1.x * v2.x * sc,
                               (acc[i][1] + bb) * v1.y * v2.y * sc,
                               (acc[i][2] + bb) * v1.z * v2.z * sc,
                               (acc[i][3] + bb) * v1.w * v2.w * sc);
        *(float4*)&Z[idx] = o;
    }
}

// ---------------- depthwise conv body ----------------
template <int KS, int DIL, int PAD>
__device__ __forceinline__ void dw_body(const float* __restrict__ xp,
                                        const float* __restrict__ wrow,
                                        float* __restrict__ yp) {
    __shared__ float tile[PP];
    __shared__ float w[KS * KS];
    for (int p = threadIdx.x; p < PP / 4; p += 256)
        ((float4*)tile)[p] = ((const float4*)xp)[p];
    if (threadIdx.x < KS * KS) w[threadIdx.x] = wrow[threadIdx.x];
    __syncthreads();
    for (int p = threadIdx.x; p < PP; p += 256) {
        int h = p >> 6, ww = p & 63;
        float s = 0.f;
#pragma unroll
        for (int kh = 0; kh < KS; kh++) {
            int hh = h + DIL * kh - PAD;
            if ((unsigned)hh >= (unsigned)HH) continue;
#pragma unroll
            for (int kw = 0; kw < KS; kw++) {
                int wc = ww + DIL * kw - PAD;
                if ((unsigned)wc >= (unsigned)WW) continue;
                s += tile[hh * WW + wc] * w[kh * KS + kw];
            }
        }
        yp[p] = s;
    }
}

template <int KS, int DIL, int PAD>
__global__ void __launch_bounds__(256) dwconv(const float* __restrict__ X,
                                              const float* __restrict__ Wd,
                                              float* __restrict__ Y) {
    int bc = blockIdx.x;
    int c = bc & (CC - 1);
    dw_body<KS, DIL, PAD>(X + (size_t)bc * PP, Wd + c * KS * KS,
                          Y + (size_t)bc * PP);
}

// two independent 3x3 depthwise convs in one launch
__global__ void __launch_bounds__(256) dw3x3_pair(const float* __restrict__ X0,
                                                  const float* __restrict__ W0,
                                                  float* __restrict__ Y0,
                                                  const float* __restrict__ X1,
                                                  const float* __restrict__ W1,
                                                  float* __restrict__ Y1) {
    int id = blockIdx.x;
    int which = id >> 9, bc = id & 511;
    int c = bc & (CC - 1);
    const float* X = which ? X1 : X0;
    const float* W = which ? W1 : W0;
    float* Y = which ? Y1 : Y0;
    dw_body<3, 1, 1>(X + (size_t)bc * PP, W + c * 9, Y + (size_t)bc * PP);
}

// ---------------- c2a grouped conv (groups=32) + SimpleGate ----------------
__global__ void __launch_bounds__(256) c2a_gate(const float* __restrict__ X,
                                                const float* __restrict__ Wg,
                                                const float* __restrict__ bg,
                                                float* __restrict__ TG) {
    int b = blockIdx.x >> 4, j = blockIdx.x & 15;
    int p0 = blockIdx.y * 512;
    __shared__ float w1[72], w2[72];
    if (threadIdx.x < 72) w1[threadIdx.x] = Wg[j * 72 + threadIdx.x];
    else if (threadIdx.x < 144) w2[threadIdx.x - 72] = Wg[(16 + j) * 72 + threadIdx.x - 72];
    __syncthreads();
    float b1 = bg[j], b2 = bg[16 + j];
    const float* x1p = X + ((size_t)b * CC + j * 8) * PP;
    const float* x2p = X + ((size_t)b * CC + (16 + j) * 8) * PP;
    for (int p = p0 + threadIdx.x; p < p0 + 512; p += 256) {
        int h = p >> 6, wq = p & 63;
        float t1 = b1, t2 = b2;
        for (int ci = 0; ci < 8; ci++) {
#pragma unroll
            for (int kh = 0; kh < 3; kh++) {
                int hh = h + kh - 1;
                if ((unsigned)hh >= (unsigned)HH) continue;
#pragma unroll
                for (int kw = 0; kw < 3; kw++) {
                    int wc = wq + kw - 1;
                    if ((unsigned)wc >= (unsigned)WW) continue;
                    float xv1 = x1p[(size_t)ci * PP + hh * WW + wc];
                    float xv2 = x2p[(size_t)ci * PP + hh * WW + wc];
                    t1 += xv1 * w1[ci * 9 + kh * 3 + kw];
                    t2 += xv2 * w2[ci * 9 + kh * 3 + kw];
                }
            }
        }
        TG[((size_t)b * 16 + j) * PP + p] = t1 * t2;
    }
}

// ---------------- att = (conv1x1(tg,c2b)+b)*gamma + attlin ----------------
__global__ void __launch_bounds__(256) att_mix(const float* __restrict__ TG,
                                               const float* __restrict__ c2bw,
                                               const float* __restrict__ c2bb,
                                               const float* __restrict__ attg,
                                               const float* __restrict__ ATTLIN,
                                               float* __restrict__ ATT) {
    int n = blockIdx.x;
    int b = blockIdx.z;
    int p0 = blockIdx.y * 1024;
    float wr[16];
#pragma unroll
    for (int q = 0; q < 16; q++) wr[q] = c2bw[n * 16 + q];
    float bb = c2bb[n], gam = attg[n];
    const float* tgb = TG + (size_t)b * 16 * PP;
    size_t base = ((size_t)b * NSET + n) * PP;
    for (int p = p0 + threadIdx.x; p < p0 + 1024; p += 256) {
        float s = bb;
#pragma unroll
        for (int q = 0; q < 16; q++) s += tgb[(size_t)q * PP + p] * wr[q];
        ATT[base + p] = s * gam + ATTLIN[base + p];
    }
}

// =========================================================================
// IKBA via warp-level tf32 mma.sync (m16n8k8). R4 structure, fast fills.
// Block = (group, 2 H-rows = 128 pixels, batch). 128 threads = 4 warps.
// A [k=128][pix=128] stride 136 (tf32 bits) — vectorized fill, and the
//   fragment loads map lanes to banks 8*l4+qr (conflict-free).
// B [n=56][k=128] stride 132: rows 0-47 w_cb cols gr*48.., rows 48-51
//   b_cb channels gr*4.. (horizontal pass only), rows 52-55 zero.
// Warp w computes rows 32w..32w+31 x all 56 cols (2 x 7 mma tiles).
// Epilogue: D -> smem (stride 57), thread=pixel applies 12-tap matvec.
// =========================================================================
#define A_ST 136
#define B_ST 132
#define IKBA_SMEM_FLOATS (128 * A_ST + 56 * B_ST)

template <int VERT>
__global__ void __launch_bounds__(128) ikba_mma(const float* __restrict__ ATT,
                                                const float* __restrict__ wcb,
                                                const float* __restrict__ bcb,
                                                const float* __restrict__ ga1,
                                                const float* __restrict__ SRC,
                                                const float* __restrict__ UFR,
                                                float* __restrict__ OUT,
                                                int halfoff) {
    extern __shared__ float sm[];
    uint32_t* Asu = (uint32_t*)sm;                // [128 k][A_ST]
    uint32_t* Bsu = (uint32_t*)(sm + 128 * A_ST); // [56 n][B_ST]
    float* Cs = sm;                               // alias post-GEMM: [128][57]

    int gr = blockIdx.x, h2 = blockIdx.y, b = blockIdx.z;
    int tid = threadIdx.x;

    // ---- A fill: thread (quad = tid&31, klane = tid>>5); LDG.128 over pixels
    {
        int quad = tid & 31, klane = tid >> 5;
        const float* ap = ATT + (size_t)b * NSET * PP + (size_t)h2 * 128 + quad * 4;
#pragma unroll 8
        for (int kk = 0; kk < 128; kk += 4) {
            int k = kk + klane;
            float4 v = *(const float4*)&ap[(size_t)k * PP];
            uint4 u = make_uint4(f2tf(v.x), f2tf(v.y), f2tf(v.z), f2tf(v.w));
            *(uint4*)&Asu[k * A_ST + quad * 4] = u;
        }
    }
    // ---- B fill rows 0..47: 128 k x 12 float4 = 1536 quads, 12 iterations
    {
        const float* wp = wcb + halfoff + gr * 48;
#pragma unroll
        for (int j = 0; j < 12; j++) {
            int l = j * 128 + tid;
            int k = l / 12, n4 = l - k * 12;
            float4 v = *(const float4*)&wp[(size_t)k * 6144 + n4 * 4];
            Bsu[(n4 * 4 + 0) * B_ST + k] = f2tf(v.x);
            Bsu[(n4 * 4 + 1) * B_ST + k] = f2tf(v.y);
            Bsu[(n4 * 4 + 2) * B_ST + k] = f2tf(v.z);
            Bsu[(n4 * 4 + 3) * B_ST + k] = f2tf(v.w);
        }
    }
    // ---- B rows 48..55: bias (horizontal) / zero
#pragma unroll
    for (int j = 0; j < 8; j++) {
        int l = j * 128 + tid;
        int k = l >> 3, n = 48 + (l & 7);
        float v = 0.f;
        if (!VERT && n < 52) v = bcb[k * CC + gr * CGC + (n - 48)];
        Bsu[n * B_ST + k] = f2tf(v);
    }
    __syncthreads();

    int warp = tid >> 5, lane = tid & 31;
    int qr = lane >> 2, l4 = lane & 3;      // qr: m-row / n-col part, l4: k part
    int m_base = warp << 5;
    float acc[2][7][4];
#pragma unroll
    for (int i = 0; i < 2; i++)
#pragma unroll
        for (int j = 0; j < 7; j++)
#pragma unroll
            for (int t = 0; t < 4; t++) acc[i][j][t] = 0.f;

    for (int k0 = 0; k0 < 128; k0 += 8) {
        uint32_t a[2][4];
        int ka = (k0 + l4) * A_ST;
#pragma unroll
        for (int mt = 0; mt < 2; mt++) {
            int row = m_base + mt * 16 + qr;
            a[mt][0] = Asu[ka + row];
            a[mt][1] = Asu[ka + row + 8];
            a[mt][2] = Asu[ka + 4 * A_ST + row];
            a[mt][3] = Asu[ka + 4 * A_ST + row + 8];
        }
#pragma unroll
        for (int nt = 0; nt < 7; nt++) {
            int nr = (nt * 8 + qr) * B_ST + k0 + l4;
            uint32_t b0 = Bsu[nr];
            uint32_t b1 = Bsu[nr + 4];
#pragma unroll
            for (int mt = 0; mt < 2; mt++) {
                asm volatile(
                    "mma.sync.aligned.m16n8k8.row.col.f32.tf32.tf32.f32 "
                    "{%0,%1,%2,%3}, {%4,%5,%6,%7}, {%8,%9}, {%0,%1,%2,%3};"
                    : "+f"(acc[mt][nt][0]), "+f"(acc[mt][nt][1]),
                      "+f"(acc[mt][nt][2]), "+f"(acc[mt][nt][3])
                    : "r"(a[mt][0]), "r"(a[mt][1]), "r"(a[mt][2]), "r"(a[mt][3]),
                      "r"(b0), "r"(b1));
            }
        }
    }
    __syncthreads();   // all Asu/Bsu reads done before alias overwrite

    // ---- store D tile: c0/c1 at (row, 2*l4 + nt*8), c2/c3 at row+8
#pragma unroll
    for (int mt = 0; mt < 2; mt++)
#pragma unroll
        for (int nt = 0; nt < 7; nt++) {
            int r = m_base + mt * 16 + qr;
            int cl = nt * 8 + 2 * l4;
            Cs[r * 57 + cl]           = acc[mt][nt][0];
            Cs[r * 57 + cl + 1]       = acc[mt][nt][1];
            Cs[(r + 8) * 57 + cl]     = acc[mt][nt][2];
            Cs[(r + 8) * 57 + cl + 1] = acc[mt][nt][3];
        }
    __syncthreads();

    // ---- epilogue: thread = pixel
    int pix = tid, r0 = pix >> 6, cp = pix & 63;
    int h = h2 * 2 + r0;
    float uf[12];
    size_t srcBase = (size_t)(b * CC + gr * CGC) * PP;
#pragma unroll
    for (int ci = 0; ci < 4; ci++)
#pragma unroll
        for (int tap = 0; tap < 3; tap++) {
            float v = 0.f;
            if (VERT) {
                int hh = h + tap - 1;
                if ((unsigned)hh < (unsigned)HH)
                    v = SRC[srcBase + (size_t)ci * PP + hh * WW + cp];
            } else {
                int wc = cp + tap - 1;
                if ((unsigned)wc < (unsigned)WW)
                    v = SRC[srcBase + (size_t)ci * PP + h * WW + wc];
            }
            uf[ci * 3 + tap] = v;
        }
    const float* cpr = &Cs[pix * 57];
#pragma unroll
    for (int oi = 0; oi < 4; oi++) {
        float s = 0.f;
#pragma unroll
        for (int j = 0; j < 12; j++) s += cpr[oi * 12 + j] * uf[j];
        size_t oidx = (size_t)(b * CC + gr * CGC + oi) * PP + (size_t)h2 * 128 + pix;
        if (VERT) {
            OUT[oidx] = s;
        } else {
            s += cpr[48 + oi];
            OUT[oidx] = s * ga1[gr * CGC + oi] + UFR[oidx];
        }
    }
}

// ---------------- launch ----------------
extern "C" void kernel_launch(void* const* d_in, const int* in_sizes, int n_in,
                              void* d_out, int out_size) {
    const float* x       = (const float*)d_in[0];
    const float* dw1_w   = (const float*)d_in[1];
    const float* dw2_w   = (const float*)d_in[2];
    const float* proj_w  = (const float*)d_in[3];
    const float* lka0_w  = (const float*)d_in[4];
    const float* lkas_w  = (const float*)d_in[5];
    const float* lka1_w  = (const float*)d_in[6];
    const float* lka1_b  = (const float*)d_in[7];
    const float* sca_w   = (const float*)d_in[8];
    const float* sca_b   = (const float*)d_in[9];
    const float* c1a_w   = (const float*)d_in[10];
    const float* c1b_w   = (const float*)d_in[11];
    const float* c2a_w   = (const float*)d_in[12];
    const float* c2a_b   = (const float*)d_in[13];
    const float* c2b_w   = (const float*)d_in[14];
    const float* c2b_b   = (const float*)d_in[15];
    const float* c211_w  = (const float*)d_in[16];
    const float* c211_b  = (const float*)d_in[17];
    const float* w_cb    = (const float*)d_in[18];
    const float* b_cb    = (const float*)d_in[19];
    const float* attgam  = (const float*)d_in[20];
    const float* ga1     = (const float*)d_in[21];
    float* out = (float*)d_out;

    float *meanb, *scab, *ydw1, *yc1a, *attlin, *x1b, *ufb, *l0, *l1,
          *tg, *att, *xh, *x2b, *zb;
    cudaGetSymbolAddress((void**)&meanb, g_mean);
    cudaGetSymbolAddress((void**)&scab, g_sca);
    cudaGetSymbolAddress((void**)&ydw1, g_ydw1);
    cudaGetSymbolAddress((void**)&yc1a, g_yc1a);
    cudaGetSymbolAddress((void**)&attlin, g_attlin);
    cudaGetSymbolAddress((void**)&x1b, g_x1);
    cudaGetSymbolAddress((void**)&ufb, g_uf);
    cudaGetSymbolAddress((void**)&l0, g_l0);
    cudaGetSymbolAddress((void**)&l1, g_l1);
    cudaGetSymbolAddress((void**)&tg, g_tg);
    cudaGetSymbolAddress((void**)&att, g_att);
    cudaGetSymbolAddress((void**)&xh, g_xh);
    cudaGetSymbolAddress((void**)&x2b, g_x2);
    cudaGetSymbolAddress((void**)&zb, g_z);

    // channel-attention branch
    meankern<<<BB * CC, 256>>>(x, meanb);
    scakern<<<BB, 256>>>(meanb, sca_w, sca_b, scab);

    // 1x1 convs from x, batched (dw1 -> ydw1, c1a -> yc1a, c211 -> attlin)
    gemm3<<<dim3(64, 10, BB), 256>>>(dw1_w, c1a_w, c211_w, c211_b, x,
                                     ydw1, yc1a, attlin);

    // depthwise chains (two 3x3 merged into one launch)
    dw3x3_pair<<<BB * CC * 2, 256>>>(ydw1, dw2_w, x1b, yc1a, c1b_w, ufb);
    dwconv<5, 1, 2><<<BB * CC, 256>>>(x, lka0_w, l0);
    dwconv<7, 3, 9><<<BB * CC, 256>>>(l0, lkas_w, l1);

    // attention map
    c2a_gate<<<dim3(BB * 16, 8), 256>>>(x, c2a_w, c2a_b, tg);
    att_mix<<<dim3(NSET, 4, BB), 256>>>(tg, c2b_w, c2b_b, attgam, attlin, att);

    // IKBA via tf32 mma.sync (fast fills)
    size_t shmem = IKBA_SMEM_FLOATS * sizeof(float);
    cudaFuncSetAttribute(ikba_mma<1>, cudaFuncAttributeMaxDynamicSharedMemorySize,
                         (int)shmem);
    cudaFuncSetAttribute(ikba_mma<0>, cudaFuncAttributeMaxDynamicSharedMemorySize,
                         (int)shmem);
    ikba_mma<1><<<dim3(GG, 32, BB), 128, shmem>>>(att, w_cb, b_cb, ga1,
                                                  ufb, nullptr, xh, 0);
    ikba_mma<0><<<dim3(GG, 32, BB), 128, shmem>>>(att, w_cb, b_cb, ga1,
                                                  xh, ufb, x2b, 3072);

    // lka1 GEMM with fused elementwise merge: z = (W@l1+b)*x1*x2*sca
    gemm_lka_ew<<<dim3(64, 4, BB), 256>>>(lka1_w, l1, lka1_b, x1b, x2b, scab, zb);

    // final projection
    gemm1x1<<<dim3(64, 4, BB), 256>>>(proj_w, zb, nullptr, out, 256, 256);
}

// round 7
// speedup vs baseline: 1.9351x; 1.0905x over previous
#include <cuda_runtime.h>
#include <cuda_bf16.h>
#include <cstdint>
#include <cstddef>

// Problem constants
#define BB 2
#define CC 256
#define HH 64
#define WW 64
#define PP 4096          // H*W
#define NSET 128
#define GG 64            // groups
#define CGC 4            // channels per group

// ---------------- scratch (device globals; no allocs allowed) ----------------
__device__ float g_mean[BB * CC];
__device__ float g_sca[BB * CC];
__device__ float g_ydw1[BB * CC * PP];
__device__ float g_yc1a[BB * CC * PP];
__device__ float g_attlin[BB * NSET * PP];
__device__ float g_x1[BB * CC * PP];
__device__ float g_uf[BB * CC * PP];
__device__ float g_l1[BB * CC * PP];
__device__ float g_tg[BB * 16 * PP];
__device__ float g_att[BB * NSET * PP];
__device__ float g_xh[BB * CC * PP];
__device__ float g_x2[BB * CC * PP];
__device__ float g_z[BB * CC * PP];

__device__ __forceinline__ uint32_t f2tf(float f) {
    uint32_t r;
    asm("cvt.rna.tf32.f32 %0, %1;" : "=r"(r) : "f"(f));
    return r;
}

#define MMA_TF32(ACC, A, B0, B1)                                              \
    asm volatile(                                                             \
        "mma.sync.aligned.m16n8k8.row.col.f32.tf32.tf32.f32 "                 \
        "{%0,%1,%2,%3}, {%4,%5,%6,%7}, {%8,%9}, {%0,%1,%2,%3};"               \
        : "+f"((ACC)[0]), "+f"((ACC)[1]), "+f"((ACC)[2]), "+f"((ACC)[3])      \
        : "r"((A)[0]), "r"((A)[1]), "r"((A)[2]), "r"((A)[3]),                 \
          "r"(B0), "r"(B1))

// ---------------- mean over H,W per (b,c) ----------------
__global__ void __launch_bounds__(256) meankern(const float* __restrict__ X,
                                                float* __restrict__ M) {
    int bc = blockIdx.x;
    const float4* xp = (const float4*)(X + (size_t)bc * PP);
    float s = 0.f;
    for (int p = threadIdx.x; p < PP / 4; p += 256) {
        float4 v = xp[p];
        s += v.x + v.y + v.z + v.w;
    }
    __shared__ float red[256];
    red[threadIdx.x] = s;
    __syncthreads();
    for (int st = 128; st > 0; st >>= 1) {
        if (threadIdx.x < st) red[threadIdx.x] += red[threadIdx.x + st];
        __syncthreads();
    }
    if (threadIdx.x == 0) M[bc] = red[0] * (1.f / PP);
}

// ---------------- sca = 1x1 conv on the mean vector ----------------
__global__ void __launch_bounds__(256) scakern(const float* __restrict__ M,
                                               const float* __restrict__ Wsca,
                                               const float* __restrict__ Bsca,
                                               float* __restrict__ SCA) {
    int b = blockIdx.x;
    int o = threadIdx.x;
    __shared__ float m[CC];
    m[o] = M[b * CC + o];
    __syncthreads();
    float s = Bsca[o];
    const float* wr = Wsca + (size_t)o * CC;
    for (int c = 0; c < CC; c++) s += wr[c] * m[c];
    SCA[b * CC + o] = s;
}

// =========================================================================
// tf32x3 1x1-conv GEMM: Y[b][m][p] = sum_k W[m][k] X[b][k][p] (+epilogue)
// Tile 64M x 128N, K chunked by 32. 256 threads = 8 warps (2m x 4n).
// A smem [m][k] stride 36 (fragment banks 4*qr+l4: conflict-free).
// B smem [k][n] stride 136 (fragment banks qr+8*l4: conflict-free).
// 3-term tf32 split: D += Ahi*Bhi + Ahi*Blo + Alo*Bhi  (fp32-like accuracy).
// MODE 0: 3-way batch (W0->Y0 M256 | W1->Y1 M256 | W2+bias->Y2 M128)
// MODE 1: Y0 = (W0 @ X + bias) * EX1 * EX2 * SCA   (lka merge)
// MODE 2: Y0 = W0 @ X                               (proj)
// =========================================================================
#define GT_SMEM_FLOATS (2 * 2304 + 2 * 4352)   // Ahi,Alo [64][36]; Bhi,Blo [32][136]

template <int MODE>
__global__ void __launch_bounds__(256) gemm_tc(
    const float* __restrict__ W0, const float* __restrict__ W1,
    const float* __restrict__ W2, const float* __restrict__ bias2,
    const float* __restrict__ X,
    float* __restrict__ Y0, float* __restrict__ Y1, float* __restrict__ Y2,
    const float* __restrict__ EX1, const float* __restrict__ EX2,
    const float* __restrict__ SCA) {
    extern __shared__ float smraw[];
    uint32_t* Ahi = (uint32_t*)smraw;              // [64][36]
    uint32_t* Alo = Ahi + 2304;
    uint32_t* Bhi = Alo + 2304;                    // [32][136]
    uint32_t* Blo = Bhi + 4352;

    int b = blockIdx.z, n0 = blockIdx.x << 7, my = blockIdx.y;
    const float* W;
    float* Y;
    const float* bias = nullptr;
    int m0, Msel;
    if (MODE == 0) {
        if (my < 4)      { W = W0; Y = Y0; m0 = my << 6; Msel = 256; }
        else if (my < 8) { W = W1; Y = Y1; m0 = (my - 4) << 6; Msel = 256; }
        else             { W = W2; Y = Y2; m0 = (my - 8) << 6; Msel = 128; bias = bias2; }
    } else {
        W = W0; Y = Y0; m0 = my << 6; Msel = 256; bias = bias2;
    }
    const float* Xb = X + (size_t)b * 256 * PP;
    int tid = threadIdx.x;
    int am = tid >> 2, akq = (tid & 3) << 3;       // A fill map
    int warp = tid >> 5, lane = tid & 31;
    int wm = warp & 1, wn = warp >> 1;
    int qr = lane >> 2, l4 = lane & 3;
    int m_warp = wm << 5, n_warp = wn << 5;
    float acc[2][4][4] = {};

    for (int k0 = 0; k0 < 256; k0 += 32) {
        // ---- A fill (64m x 32k): LDG.128 along k, hi/lo split
        {
            const float* wr = &W[(size_t)(m0 + am) * 256 + k0 + akq];
            float4 v0 = *(const float4*)wr;
            float4 v1 = *(const float4*)(wr + 4);
            uint4 h0, h1, q0, q1;
            h0.x = f2tf(v0.x); h0.y = f2tf(v0.y); h0.z = f2tf(v0.z); h0.w = f2tf(v0.w);
            h1.x = f2tf(v1.x); h1.y = f2tf(v1.y); h1.z = f2tf(v1.z); h1.w = f2tf(v1.w);
            q0.x = f2tf(v0.x - __uint_as_float(h0.x));
            q0.y = f2tf(v0.y - __uint_as_float(h0.y));
            q0.z = f2tf(v0.z - __uint_as_float(h0.z));
            q0.w = f2tf(v0.w - __uint_as_float(h0.w));
            q1.x = f2tf(v1.x - __uint_as_float(h1.x));
            q1.y = f2tf(v1.y - __uint_as_float(h1.y));
            q1.z = f2tf(v1.z - __uint_as_float(h1.z));
            q1.w = f2tf(v1.w - __uint_as_float(h1.w));
            int base = am * 36 + akq;
            *(uint4*)&Ahi[base] = h0;  *(uint4*)&Ahi[base + 4] = h1;
            *(uint4*)&Alo[base] = q0;  *(uint4*)&Alo[base + 4] = q1;
        }
        // ---- B fill (32k x 128n): contiguous LDG.128 along n
#pragma unroll
        for (int j = 0; j < 4; j++) {
            int idx = tid + (j << 8);
            int kk = idx >> 5, nq = idx & 31;
            float4 v = *(const float4*)&Xb[(size_t)(k0 + kk) * PP + n0 + (nq << 2)];
            uint4 h, q;
            h.x = f2tf(v.x); h.y = f2tf(v.y); h.z = f2tf(v.z); h.w = f2tf(v.w);
            q.x = f2tf(v.x - __uint_as_float(h.x));
            q.y = f2tf(v.y - __uint_as_float(h.y));
            q.z = f2tf(v.z - __uint_as_float(h.z));
            q.w = f2tf(v.w - __uint_as_float(h.w));
            int base = kk * 136 + (nq << 2);
            *(uint4*)&Bhi[base] = h;
            *(uint4*)&Blo[base] = q;
        }
        __syncthreads();

#pragma unroll
        for (int ks = 0; ks < 32; ks += 8) {
            uint32_t ah[2][4], al[2][4];
#pragma unroll
            for (int mt = 0; mt < 2; mt++) {
                int r0 = (m_warp + mt * 16 + qr) * 36 + ks + l4;
                int r1 = r0 + 8 * 36;
                ah[mt][0] = Ahi[r0]; ah[mt][1] = Ahi[r1];
                ah[mt][2] = Ahi[r0 + 4]; ah[mt][3] = Ahi[r1 + 4];
                al[mt][0] = Alo[r0]; al[mt][1] = Alo[r1];
                al[mt][2] = Alo[r0 + 4]; al[mt][3] = Alo[r1 + 4];
            }
#pragma unroll
            for (int nt = 0; nt < 4; nt++) {
                int ncol = n_warp + nt * 8 + qr;
                int kb0 = (ks + l4) * 136 + ncol;
                int kb1 = kb0 + 4 * 136;
                uint32_t bh0 = Bhi[kb0], bh1 = Bhi[kb1];
                uint32_t bl0 = Blo[kb0], bl1 = Blo[kb1];
#pragma unroll
                for (int mt = 0; mt < 2; mt++) {
                    MMA_TF32(acc[mt][nt], ah[mt], bh0, bh1);
                    MMA_TF32(acc[mt][nt], ah[mt], bl0, bl1);
                    MMA_TF32(acc[mt][nt], al[mt], bh0, bh1);
                }
            }
        }
        __syncthreads();
    }

    // ---- epilogue
    float* Yb = Y + (size_t)b * Msel * PP;
#pragma unroll
    for (int mt = 0; mt < 2; mt++)
#pragma unroll
        for (int nt = 0; nt < 4; nt++) {
            int row = m_warp + mt * 16 + qr;
            int col = n_warp + nt * 8 + (l4 << 1);
#pragma unroll
            for (int rr = 0; rr < 2; rr++) {
                int rm = m0 + row + rr * 8;
                float c0 = acc[mt][nt][rr * 2], c1 = acc[mt][nt][rr * 2 + 1];
                size_t yidx = (size_t)(row + rr * 8 + m0) * PP + n0 + col;
                if (MODE == 1) {
                    float bb = bias[rm];
                    float sc = SCA[b * CC + rm];
                    size_t gidx = (size_t)b * CC * PP + (size_t)rm * PP + n0 + col;
                    float2 v1 = *(const float2*)&EX1[gidx];
                    float2 v2 = *(const float2*)&EX2[gidx];
                    float2 o = make_float2((c0 + bb) * v1.x * v2.x * sc,
                                           (c1 + bb) * v1.y * v2.y * sc);
                    *(float2*)&Yb[yidx] = o;
                } else {
                    float bb = (MODE == 0 && bias) ? bias[rm] : 0.f;
                    *(float2*)&Yb[yidx] = make_float2(c0 + bb, c1 + bb);
                }
            }
        }
}

// ---------------- depthwise conv body ----------------
template <int KS, int DIL, int PAD>
__device__ __forceinline__ void dw_conv_tile(const float* __restrict__ tile,
                                             const float* __restrict__ w,
                                             float* __restrict__ outf,
                                             bool to_smem, float* smout,
                                             float* gout) {
    for (int p = threadIdx.x; p < PP; p += 256) {
        int h = p >> 6, ww = p & 63;
        float s = 0.f;
#pragma unroll
        for (int kh = 0; kh < KS; kh++) {
            int hh = h + DIL * kh - PAD;
            if ((unsigned)hh >= (unsigned)HH) continue;
#pragma unroll
            for (int kw = 0; kw < KS; kw++) {
                int wc = ww + DIL * kw - PAD;
                if ((unsigned)wc >= (unsigned)WW) continue;
                s += tile[hh * WW + wc] * w[kh * KS + kw];
            }
        }
        if (to_smem) smout[p] = s;
        else gout[p] = s;
    }
}

// two independent 3x3 depthwise convs in one launch
__global__ void __launch_bounds__(256) dw3x3_pair(const float* __restrict__ X0,
                                                  const float* __restrict__ W0,
                                                  float* __restrict__ Y0,
                                                  const float* __restrict__ X1,
                                                  const float* __restrict__ W1,
                                                  float* __restrict__ Y1) {
    __shared__ float tile[PP];
    __shared__ float w[9];
    int id = blockIdx.x;
    int which = id >> 9, bc = id & 511;
    int c = bc & (CC - 1);
    const float* X = which ? X1 : X0;
    const float* Wd = which ? W1 : W0;
    float* Y = which ? Y1 : Y0;
    const float4* xp = (const float4*)(X + (size_t)bc * PP);
    for (int p = threadIdx.x; p < PP / 4; p += 256)
        ((float4*)tile)[p] = xp[p];
    if (threadIdx.x < 9) w[threadIdx.x] = Wd[c * 9 + threadIdx.x];
    __syncthreads();
    dw_conv_tile<3, 1, 1>(tile, w, nullptr, false, nullptr,
                          Y + (size_t)bc * PP);
}

// fused LKA depthwise chain: 5x5 pad2 -> 7x7 dil3 pad9 (l0 stays in smem)
__global__ void __launch_bounds__(256) lka_chain(const float* __restrict__ X,
                                                 const float* __restrict__ W5,
                                                 const float* __restrict__ W7,
                                                 float* __restrict__ OUT) {
    __shared__ float t0[PP];
    __shared__ float t1[PP];
    __shared__ float w5[25], w7[49];
    int bc = blockIdx.x;
    int c = bc & (CC - 1);
    const float4* xp = (const float4*)(X + (size_t)bc * PP);
    for (int p = threadIdx.x; p < PP / 4; p += 256)
        ((float4*)t0)[p] = xp[p];
    if (threadIdx.x < 25) w5[threadIdx.x] = W5[c * 25 + threadIdx.x];
    else if (threadIdx.x >= 32 && threadIdx.x < 81)
        w7[threadIdx.x - 32] = W7[c * 49 + threadIdx.x - 32];
    __syncthreads();
    dw_conv_tile<5, 1, 2>(t0, w5, nullptr, true, t1, nullptr);
    __syncthreads();
    dw_conv_tile<7, 3, 9>(t1, w7, nullptr, false, nullptr,
                          OUT + (size_t)bc * PP);
}

// ---------------- c2a grouped conv (groups=32) + SimpleGate ----------------
__global__ void __launch_bounds__(256) c2a_gate(const float* __restrict__ X,
                                                const float* __restrict__ Wg,
                                                const float* __restrict__ bg,
                                                float* __restrict__ TG) {
    int b = blockIdx.x >> 4, j = blockIdx.x & 15;
    int p0 = blockIdx.y * 512;
    __shared__ float w1[72], w2[72];
    if (threadIdx.x < 72) w1[threadIdx.x] = Wg[j * 72 + threadIdx.x];
    else if (threadIdx.x < 144) w2[threadIdx.x - 72] = Wg[(16 + j) * 72 + threadIdx.x - 72];
    __syncthreads();
    float b1 = bg[j], b2 = bg[16 + j];
    const float* x1p = X + ((size_t)b * CC + j * 8) * PP;
    const float* x2p = X + ((size_t)b * CC + (16 + j) * 8) * PP;
    for (int p = p0 + threadIdx.x; p < p0 + 512; p += 256) {
        int h = p >> 6, wq = p & 63;
        float t1 = b1, t2 = b2;
        for (int ci = 0; ci < 8; ci++) {
#pragma unroll
            for (int kh = 0; kh < 3; kh++) {
                int hh = h + kh - 1;
                if ((unsigned)hh >= (unsigned)HH) continue;
#pragma unroll
                for (int kw = 0; kw < 3; kw++) {
                    int wc = wq + kw - 1;
                    if ((unsigned)wc >= (unsigned)WW) continue;
                    float xv1 = x1p[(size_t)ci * PP + hh * WW + wc];
                    float xv2 = x2p[(size_t)ci * PP + hh * WW + wc];
                    t1 += xv1 * w1[ci * 9 + kh * 3 + kw];
                    t2 += xv2 * w2[ci * 9 + kh * 3 + kw];
                }
            }
        }
        TG[((size_t)b * 16 + j) * PP + p] = t1 * t2;
    }
}

// ---------------- att = (conv1x1(tg,c2b)+b)*gamma + attlin ----------------
__global__ void __launch_bounds__(256) att_mix(const float* __restrict__ TG,
                                               const float* __restrict__ c2bw,
                                               const float* __restrict__ c2bb,
                                               const float* __restrict__ attg,
                                               const float* __restrict__ ATTLIN,
                                               float* __restrict__ ATT) {
    int n = blockIdx.x;
    int b = blockIdx.z;
    int p0 = blockIdx.y * 1024;
    float wr[16];
#pragma unroll
    for (int q = 0; q < 16; q++) wr[q] = c2bw[n * 16 + q];
    float bb = c2bb[n], gam = attg[n];
    const float* tgb = TG + (size_t)b * 16 * PP;
    size_t base = ((size_t)b * NSET + n) * PP;
    for (int p = p0 + threadIdx.x; p < p0 + 1024; p += 256) {
        float s = bb;
#pragma unroll
        for (int q = 0; q < 16; q++) s += tgb[(size_t)q * PP + p] * wr[q];
        ATT[base + p] = s * gam + ATTLIN[base + p];
    }
}

// =========================================================================
// IKBA via warp-level tf32 mma.sync (m16n8k8). Proven R6 version.
// =========================================================================
#define A_ST 136
#define B_ST 132
#define IKBA_SMEM_FLOATS (128 * A_ST + 56 * B_ST)

template <int VERT>
__global__ void __launch_bounds__(128) ikba_mma(const float* __restrict__ ATT,
                                                const float* __restrict__ wcb,
                                                const float* __restrict__ bcb,
                                                const float* __restrict__ ga1,
                                                const float* __restrict__ SRC,
                                                const float* __restrict__ UFR,
                                                float* __restrict__ OUT,
                                                int halfoff) {
    extern __shared__ float sm[];
    uint32_t* Asu = (uint32_t*)sm;                // [128 k][A_ST]
    uint32_t* Bsu = (uint32_t*)(sm + 128 * A_ST); // [56 n][B_ST]
    float* Cs = sm;                               // alias post-GEMM: [128][57]

    int gr = blockIdx.x, h2 = blockIdx.y, b = blockIdx.z;
    int tid = threadIdx.x;

    {
        int quad = tid & 31, klane = tid >> 5;
        const float* ap = ATT + (size_t)b * NSET * PP + (size_t)h2 * 128 + quad * 4;
#pragma unroll 8
        for (int kk = 0; kk < 128; kk += 4) {
            int k = kk + klane;
            float4 v = *(const float4*)&ap[(size_t)k * PP];
            uint4 u = make_uint4(f2tf(v.x), f2tf(v.y), f2tf(v.z), f2tf(v.w));
            *(uint4*)&Asu[k * A_ST + quad * 4] = u;
        }
    }
    {
        const float* wp = wcb + halfoff + gr * 48;
#pragma unroll
        for (int j = 0; j < 12; j++) {
            int l = j * 128 + tid;
            int k = l / 12, n4 = l - k * 12;
            float4 v = *(const float4*)&wp[(size_t)k * 6144 + n4 * 4];
            Bsu[(n4 * 4 + 0) * B_ST + k] = f2tf(v.x);
            Bsu[(n4 * 4 + 1) * B_ST + k] = f2tf(v.y);
            Bsu[(n4 * 4 + 2) * B_ST + k] = f2tf(v.z);
            Bsu[(n4 * 4 + 3) * B_ST + k] = f2tf(v.w);
        }
    }
#pragma unroll
    for (int j = 0; j < 8; j++) {
        int l = j * 128 + tid;
        int k = l >> 3, n = 48 + (l & 7);
        float v = 0.f;
        if (!VERT && n < 52) v = bcb[k * CC + gr * CGC + (n - 48)];
        Bsu[n * B_ST + k] = f2tf(v);
    }
    __syncthreads();

    int warp = tid >> 5, lane = tid & 31;
    int qr = lane >> 2, l4 = lane & 3;
    int m_base = warp << 5;
    float acc[2][7][4];
#pragma unroll
    for (int i = 0; i < 2; i++)
#pragma unroll
        for (int j = 0; j < 7; j++)
#pragma unroll
            for (int t = 0; t < 4; t++) acc[i][j][t] = 0.f;

    for (int k0 = 0; k0 < 128; k0 += 8) {
        uint32_t a[2][4];
        int ka = (k0 + l4) * A_ST;
#pragma unroll
        for (int mt = 0; mt < 2; mt++) {
            int row = m_base + mt * 16 + qr;
            a[mt][0] = Asu[ka + row];
            a[mt][1] = Asu[ka + row + 8];
            a[mt][2] = Asu[ka + 4 * A_ST + row];
            a[mt][3] = Asu[ka + 4 * A_ST + row + 8];
        }
#pragma unroll
        for (int nt = 0; nt < 7; nt++) {
            int nr = (nt * 8 + qr) * B_ST + k0 + l4;
            uint32_t b0 = Bsu[nr];
            uint32_t b1 = Bsu[nr + 4];
#pragma unroll
            for (int mt = 0; mt < 2; mt++) {
                MMA_TF32(acc[mt][nt], a[mt], b0, b1);
            }
        }
    }
    __syncthreads();

#pragma unroll
    for (int mt = 0; mt < 2; mt++)
#pragma unroll
        for (int nt = 0; nt < 7; nt++) {
            int r = m_base + mt * 16 + qr;
            int cl = nt * 8 + 2 * l4;
            Cs[r * 57 + cl]           = acc[mt][nt][0];
            Cs[r * 57 + cl + 1]       = acc[mt][nt][1];
            Cs[(r + 8) * 57 + cl]     = acc[mt][nt][2];
            Cs[(r + 8) * 57 + cl + 1] = acc[mt][nt][3];
        }
    __syncthreads();

    int pix = tid, r0 = pix >> 6, cp = pix & 63;
    int h = h2 * 2 + r0;
    float uf[12];
    size_t srcBase = (size_t)(b * CC + gr * CGC) * PP;
#pragma unroll
    for (int ci = 0; ci < 4; ci++)
#pragma unroll
        for (int tap = 0; tap < 3; tap++) {
            float v = 0.f;
            if (VERT) {
                int hh = h + tap - 1;
                if ((unsigned)hh < (unsigned)HH)
                    v = SRC[srcBase + (size_t)ci * PP + hh * WW + cp];
            } else {
                int wc = cp + tap - 1;
                if ((unsigned)wc < (unsigned)WW)
                    v = SRC[srcBase + (size_t)ci * PP + h * WW + wc];
            }
            uf[ci * 3 + tap] = v;
        }
    const float* cpr = &Cs[pix * 57];
#pragma unroll
    for (int oi = 0; oi < 4; oi++) {
        float s = 0.f;
#pragma unroll
        for (int j = 0; j < 12; j++) s += cpr[oi * 12 + j] * uf[j];
        size_t oidx = (size_t)(b * CC + gr * CGC + oi) * PP + (size_t)h2 * 128 + pix;
        if (VERT) {
            OUT[oidx] = s;
        } else {
            s += cpr[48 + oi];
            OUT[oidx] = s * ga1[gr * CGC + oi] + UFR[oidx];
        }
    }
}

// ---------------- launch ----------------
extern "C" void kernel_launch(void* const* d_in, const int* in_sizes, int n_in,
                              void* d_out, int out_size) {
    const float* x       = (const float*)d_in[0];
    const float* dw1_w   = (const float*)d_in[1];
    const float* dw2_w   = (const float*)d_in[2];
    const float* proj_w  = (const float*)d_in[3];
    const float* lka0_w  = (const float*)d_in[4];
    const float* lkas_w  = (const float*)d_in[5];
    const float* lka1_w  = (const float*)d_in[6];
    const float* lka1_b  = (const float*)d_in[7];
    const float* sca_w   = (const float*)d_in[8];
    const float* sca_b   = (const float*)d_in[9];
    const float* c1a_w   = (const float*)d_in[10];
    const float* c1b_w   = (const float*)d_in[11];
    const float* c2a_w   = (const float*)d_in[12];
    const float* c2a_b   = (const float*)d_in[13];
    const float* c2b_w   = (const float*)d_in[14];
    const float* c2b_b   = (const float*)d_in[15];
    const float* c211_w  = (const float*)d_in[16];
    const float* c211_b  = (const float*)d_in[17];
    const float* w_cb    = (const float*)d_in[18];
    const float* b_cb    = (const float*)d_in[19];
    const float* attgam  = (const float*)d_in[20];
    const float* ga1     = (const float*)d_in[21];
    float* out = (float*)d_out;

    float *meanb, *scab, *ydw1, *yc1a, *attlin, *x1b, *ufb, *l1,
          *tg, *att, *xh, *x2b, *zb;
    cudaGetSymbolAddress((void**)&meanb, g_mean);
    cudaGetSymbolAddress((void**)&scab, g_sca);
    cudaGetSymbolAddress((void**)&ydw1, g_ydw1);
    cudaGetSymbolAddress((void**)&yc1a, g_yc1a);
    cudaGetSymbolAddress((void**)&attlin, g_attlin);
    cudaGetSymbolAddress((void**)&x1b, g_x1);
    cudaGetSymbolAddress((void**)&ufb, g_uf);
    cudaGetSymbolAddress((void**)&l1, g_l1);
    cudaGetSymbolAddress((void**)&tg, g_tg);
    cudaGetSymbolAddress((void**)&att, g_att);
    cudaGetSymbolAddress((void**)&xh, g_xh);
    cudaGetSymbolAddress((void**)&x2b, g_x2);
    cudaGetSymbolAddress((void**)&zb, g_z);

    size_t gt_smem = GT_SMEM_FLOATS * sizeof(float);
    cudaFuncSetAttribute(gemm_tc<0>, cudaFuncAttributeMaxDynamicSharedMemorySize,
                         (int)gt_smem);
    cudaFuncSetAttribute(gemm_tc<1>, cudaFuncAttributeMaxDynamicSharedMemorySize,
                         (int)gt_smem);
    cudaFuncSetAttribute(gemm_tc<2>, cudaFuncAttributeMaxDynamicSharedMemorySize,
                         (int)gt_smem);

    // channel-attention branch
    meankern<<<BB * CC, 256>>>(x, meanb);
    scakern<<<BB, 256>>>(meanb, sca_w, sca_b, scab);

    // 1x1 convs from x, batched (dw1 -> ydw1, c1a -> yc1a, c211 -> attlin)
    gemm_tc<0><<<dim3(32, 10, BB), 256, gt_smem>>>(
        dw1_w, c1a_w, c211_w, c211_b, x, ydw1, yc1a, attlin,
        nullptr, nullptr, nullptr);

    // depthwise chains
    dw3x3_pair<<<BB * CC * 2, 256>>>(ydw1, dw2_w, x1b, yc1a, c1b_w, ufb);
    lka_chain<<<BB * CC, 256>>>(x, lka0_w, lkas_w, l1);

    // attention map
    c2a_gate<<<dim3(BB * 16, 8), 256>>>(x, c2a_w, c2a_b, tg);
    att_mix<<<dim3(NSET, 4, BB), 256>>>(tg, c2b_w, c2b_b, attgam, attlin, att);

    // IKBA via tf32 mma.sync (fast fills)
    size_t shmem = IKBA_SMEM_FLOATS * sizeof(float);
    cudaFuncSetAttribute(ikba_mma<1>, cudaFuncAttributeMaxDynamicSharedMemorySize,
                         (int)shmem);
    cudaFuncSetAttribute(ikba_mma<0>, cudaFuncAttributeMaxDynamicSharedMemorySize,
                         (int)shmem);
    ikba_mma<1><<<dim3(GG, 32, BB), 128, shmem>>>(att, w_cb, b_cb, ga1,
                                                  ufb, nullptr, xh, 0);
    ikba_mma<0><<<dim3(GG, 32, BB), 128, shmem>>>(att, w_cb, b_cb, ga1,
                                                  xh, ufb, x2b, 3072);

    // lka1 GEMM with fused elementwise merge: z = (W@l1+b)*x1*x2*sca
    gemm_tc<1><<<dim3(32, 4, BB), 256, gt_smem>>>(
        lka1_w, nullptr, nullptr, lka1_b, l1, zb, nullptr, nullptr,
        x1b, x2b, scab);

    // final projection
    gemm_tc<2><<<dim3(32, 4, BB), 256, gt_smem>>>(
        proj_w, nullptr, nullptr, nullptr, zb, out, nullptr, nullptr,
        nullptr, nullptr, nullptr);
}

// round 8
// speedup vs baseline: 2.1090x; 1.0899x over previous
#include <cuda_runtime.h>
#include <cuda_bf16.h>
#include <cstdint>
#include <cstddef>

// Problem constants
#define BB 2
#define CC 256
#define HH 64
#define WW 64
#define PP 4096          // H*W
#define NSET 128
#define GG 64            // groups
#define CGC 4            // channels per group

// ---------------- scratch (device globals; no allocs allowed) ----------------
__device__ float g_mean[BB * CC];
__device__ float g_sca[BB * CC];
__device__ float g_ydw1[BB * CC * PP];
__device__ float g_yc1a[BB * CC * PP];
__device__ float g_attlin[BB * NSET * PP];
__device__ float g_x1[BB * CC * PP];
__device__ float g_uf[BB * CC * PP];
__device__ float g_l1[BB * CC * PP];
__device__ float g_tg[BB * 16 * PP];
__device__ float g_att[BB * NSET * PP];
__device__ float g_x2[BB * CC * PP];
__device__ float g_z[BB * CC * PP];

__device__ __forceinline__ uint32_t f2tf(float f) {
    uint32_t r;
    asm("cvt.rna.tf32.f32 %0, %1;" : "=r"(r) : "f"(f));
    return r;
}

#define MMA_TF32(ACC, A, B0, B1)                                              \
    asm volatile(                                                             \
        "mma.sync.aligned.m16n8k8.row.col.f32.tf32.tf32.f32 "                 \
        "{%0,%1,%2,%3}, {%4,%5,%6,%7}, {%8,%9}, {%0,%1,%2,%3};"               \
        : "+f"((ACC)[0]), "+f"((ACC)[1]), "+f"((ACC)[2]), "+f"((ACC)[3])      \
        : "r"((A)[0]), "r"((A)[1]), "r"((A)[2]), "r"((A)[3]),                 \
          "r"(B0), "r"(B1))

// ---------------- mean over H,W per (b,c) ----------------
__global__ void __launch_bounds__(256) meankern(const float* __restrict__ X,
                                                float* __restrict__ M) {
    int bc = blockIdx.x;
    const float4* xp = (const float4*)(X + (size_t)bc * PP);
    float s = 0.f;
    for (int p = threadIdx.x; p < PP / 4; p += 256) {
        float4 v = xp[p];
        s += v.x + v.y + v.z + v.w;
    }
    __shared__ float red[256];
    red[threadIdx.x] = s;
    __syncthreads();
    for (int st = 128; st > 0; st >>= 1) {
        if (threadIdx.x < st) red[threadIdx.x] += red[threadIdx.x + st];
        __syncthreads();
    }
    if (threadIdx.x == 0) M[bc] = red[0] * (1.f / PP);
}

// ---------------- sca = 1x1 conv on the mean vector ----------------
__global__ void __launch_bounds__(256) scakern(const float* __restrict__ M,
                                               const float* __restrict__ Wsca,
                                               const float* __restrict__ Bsca,
                                               float* __restrict__ SCA) {
    int b = blockIdx.x;
    int o = threadIdx.x;
    __shared__ float m[CC];
    m[o] = M[b * CC + o];
    __syncthreads();
    float s = Bsca[o];
    const float* wr = Wsca + (size_t)o * CC;
    for (int c = 0; c < CC; c++) s += wr[c] * m[c];
    SCA[b * CC + o] = s;
}

// =========================================================================
// tf32x3 1x1-conv GEMM (proven R7). Tile 64M x 128N, 8 warps (2m x 4n).
// MODE 0: 3-way batch | MODE 1: lka merge epilogue | MODE 2: plain
// =========================================================================
#define GT_SMEM_FLOATS (2 * 2304 + 2 * 4352)

template <int MODE>
__global__ void __launch_bounds__(256) gemm_tc(
    const float* __restrict__ W0, const float* __restrict__ W1,
    const float* __restrict__ W2, const float* __restrict__ bias2,
    const float* __restrict__ X,
    float* __restrict__ Y0, float* __restrict__ Y1, float* __restrict__ Y2,
    const float* __restrict__ EX1, const float* __restrict__ EX2,
    const float* __restrict__ SCA) {
    extern __shared__ float smraw[];
    uint32_t* Ahi = (uint32_t*)smraw;              // [64][36]
    uint32_t* Alo = Ahi + 2304;
    uint32_t* Bhi = Alo + 2304;                    // [32][136]
    uint32_t* Blo = Bhi + 4352;

    int b = blockIdx.z, n0 = blockIdx.x << 7, my = blockIdx.y;
    const float* W;
    float* Y;
    const float* bias = nullptr;
    int m0, Msel;
    if (MODE == 0) {
        if (my < 4)      { W = W0; Y = Y0; m0 = my << 6; Msel = 256; }
        else if (my < 8) { W = W1; Y = Y1; m0 = (my - 4) << 6; Msel = 256; }
        else             { W = W2; Y = Y2; m0 = (my - 8) << 6; Msel = 128; bias = bias2; }
    } else {
        W = W0; Y = Y0; m0 = my << 6; Msel = 256; bias = bias2;
    }
    const float* Xb = X + (size_t)b * 256 * PP;
    int tid = threadIdx.x;
    int am = tid >> 2, akq = (tid & 3) << 3;
    int warp = tid >> 5, lane = tid & 31;
    int wm = warp & 1, wn = warp >> 1;
    int qr = lane >> 2, l4 = lane & 3;
    int m_warp = wm << 5, n_warp = wn << 5;
    float acc[2][4][4] = {};

    for (int k0 = 0; k0 < 256; k0 += 32) {
        {
            const float* wr = &W[(size_t)(m0 + am) * 256 + k0 + akq];
            float4 v0 = *(const float4*)wr;
            float4 v1 = *(const float4*)(wr + 4);
            uint4 h0, h1, q0, q1;
            h0.x = f2tf(v0.x); h0.y = f2tf(v0.y); h0.z = f2tf(v0.z); h0.w = f2tf(v0.w);
            h1.x = f2tf(v1.x); h1.y = f2tf(v1.y); h1.z = f2tf(v1.z); h1.w = f2tf(v1.w);
            q0.x = f2tf(v0.x - __uint_as_float(h0.x));
            q0.y = f2tf(v0.y - __uint_as_float(h0.y));
            q0.z = f2tf(v0.z - __uint_as_float(h0.z));
            q0.w = f2tf(v0.w - __uint_as_float(h0.w));
            q1.x = f2tf(v1.x - __uint_as_float(h1.x));
            q1.y = f2tf(v1.y - __uint_as_float(h1.y));
            q1.z = f2tf(v1.z - __uint_as_float(h1.z));
            q1.w = f2tf(v1.w - __uint_as_float(h1.w));
            int base = am * 36 + akq;
            *(uint4*)&Ahi[base] = h0;  *(uint4*)&Ahi[base + 4] = h1;
            *(uint4*)&Alo[base] = q0;  *(uint4*)&Alo[base + 4] = q1;
        }
#pragma unroll
        for (int j = 0; j < 4; j++) {
            int idx = tid + (j << 8);
            int kk = idx >> 5, nq = idx & 31;
            float4 v = *(const float4*)&Xb[(size_t)(k0 + kk) * PP + n0 + (nq << 2)];
            uint4 h, q;
            h.x = f2tf(v.x); h.y = f2tf(v.y); h.z = f2tf(v.z); h.w = f2tf(v.w);
            q.x = f2tf(v.x - __uint_as_float(h.x));
            q.y = f2tf(v.y - __uint_as_float(h.y));
            q.z = f2tf(v.z - __uint_as_float(h.z));
            q.w = f2tf(v.w - __uint_as_float(h.w));
            int base = kk * 136 + (nq << 2);
            *(uint4*)&Bhi[base] = h;
            *(uint4*)&Blo[base] = q;
        }
        __syncthreads();

#pragma unroll
        for (int ks = 0; ks < 32; ks += 8) {
            uint32_t ah[2][4], al[2][4];
#pragma unroll
            for (int mt = 0; mt < 2; mt++) {
                int r0 = (m_warp + mt * 16 + qr) * 36 + ks + l4;
                int r1 = r0 + 8 * 36;
                ah[mt][0] = Ahi[r0]; ah[mt][1] = Ahi[r1];
                ah[mt][2] = Ahi[r0 + 4]; ah[mt][3] = Ahi[r1 + 4];
                al[mt][0] = Alo[r0]; al[mt][1] = Alo[r1];
                al[mt][2] = Alo[r0 + 4]; al[mt][3] = Alo[r1 + 4];
            }
#pragma unroll
            for (int nt = 0; nt < 4; nt++) {
                int ncol = n_warp + nt * 8 + qr;
                int kb0 = (ks + l4) * 136 + ncol;
                int kb1 = kb0 + 4 * 136;
                uint32_t bh0 = Bhi[kb0], bh1 = Bhi[kb1];
                uint32_t bl0 = Blo[kb0], bl1 = Blo[kb1];
#pragma unroll
                for (int mt = 0; mt < 2; mt++) {
                    MMA_TF32(acc[mt][nt], ah[mt], bh0, bh1);
                    MMA_TF32(acc[mt][nt], ah[mt], bl0, bl1);
                    MMA_TF32(acc[mt][nt], al[mt], bh0, bh1);
                }
            }
        }
        __syncthreads();
    }

    float* Yb = Y + (size_t)b * Msel * PP;
#pragma unroll
    for (int mt = 0; mt < 2; mt++)
#pragma unroll
        for (int nt = 0; nt < 4; nt++) {
            int row = m_warp + mt * 16 + qr;
            int col = n_warp + nt * 8 + (l4 << 1);
#pragma unroll
            for (int rr = 0; rr < 2; rr++) {
                int rm = m0 + row + rr * 8;
                float c0 = acc[mt][nt][rr * 2], c1 = acc[mt][nt][rr * 2 + 1];
                size_t yidx = (size_t)(row + rr * 8 + m0) * PP + n0 + col;
                if (MODE == 1) {
                    float bb = bias[rm];
                    float sc = SCA[b * CC + rm];
                    size_t gidx = (size_t)b * CC * PP + (size_t)rm * PP + n0 + col;
                    float2 v1 = *(const float2*)&EX1[gidx];
                    float2 v2 = *(const float2*)&EX2[gidx];
                    float2 o = make_float2((c0 + bb) * v1.x * v2.x * sc,
                                           (c1 + bb) * v1.y * v2.y * sc);
                    *(float2*)&Yb[yidx] = o;
                } else {
                    float bb = (MODE == 0 && bias) ? bias[rm] : 0.f;
                    *(float2*)&Yb[yidx] = make_float2(c0 + bb, c1 + bb);
                }
            }
        }
}

// ---------------- depthwise conv body ----------------
template <int KS, int DIL, int PAD>
__device__ __forceinline__ void dw_conv_tile(const float* __restrict__ tile,
                                             const float* __restrict__ w,
                                             bool to_smem, float* smout,
                                             float* gout) {
    for (int p = threadIdx.x; p < PP; p += 256) {
        int h = p >> 6, ww = p & 63;
        float s = 0.f;
#pragma unroll
        for (int kh = 0; kh < KS; kh++) {
            int hh = h + DIL * kh - PAD;
            if ((unsigned)hh >= (unsigned)HH) continue;
#pragma unroll
            for (int kw = 0; kw < KS; kw++) {
                int wc = ww + DIL * kw - PAD;
                if ((unsigned)wc >= (unsigned)WW) continue;
                s += tile[hh * WW + wc] * w[kh * KS + kw];
            }
        }
        if (to_smem) smout[p] = s;
        else gout[p] = s;
    }
}

// two independent 3x3 depthwise convs in one launch
__global__ void __launch_bounds__(256) dw3x3_pair(const float* __restrict__ X0,
                                                  const float* __restrict__ W0,
                                                  float* __restrict__ Y0,
                                                  const float* __restrict__ X1,
                                                  const float* __restrict__ W1,
                                                  float* __restrict__ Y1) {
    __shared__ float tile[PP];
    __shared__ float w[9];
    int id = blockIdx.x;
    int which = id >> 9, bc = id & 511;
    int c = bc & (CC - 1);
    const float* X = which ? X1 : X0;
    const float* Wd = which ? W1 : W0;
    float* Y = which ? Y1 : Y0;
    const float4* xp = (const float4*)(X + (size_t)bc * PP);
    for (int p = threadIdx.x; p < PP / 4; p += 256)
        ((float4*)tile)[p] = xp[p];
    if (threadIdx.x < 9) w[threadIdx.x] = Wd[c * 9 + threadIdx.x];
    __syncthreads();
    dw_conv_tile<3, 1, 1>(tile, w, false, nullptr, Y + (size_t)bc * PP);
}

// fused LKA depthwise chain: 5x5 pad2 -> 7x7 dil3 pad9 (l0 stays in smem)
__global__ void __launch_bounds__(256) lka_chain(const float* __restrict__ X,
                                                 const float* __restrict__ W5,
                                                 const float* __restrict__ W7,
                                                 float* __restrict__ OUT) {
    __shared__ float t0[PP];
    __shared__ float t1[PP];
    __shared__ float w5[25], w7[49];
    int bc = blockIdx.x;
    int c = bc & (CC - 1);
    const float4* xp = (const float4*)(X + (size_t)bc * PP);
    for (int p = threadIdx.x; p < PP / 4; p += 256)
        ((float4*)t0)[p] = xp[p];
    if (threadIdx.x < 25) w5[threadIdx.x] = W5[c * 25 + threadIdx.x];
    else if (threadIdx.x >= 32 && threadIdx.x < 81)
        w7[threadIdx.x - 32] = W7[c * 49 + threadIdx.x - 32];
    __syncthreads();
    dw_conv_tile<5, 1, 2>(t0, w5, true, t1, nullptr);
    __syncthreads();
    dw_conv_tile<7, 3, 9>(t1, w7, false, nullptr, OUT + (size_t)bc * PP);
}

// ---------------- c2a grouped conv (groups=32) + SimpleGate ----------------
__global__ void __launch_bounds__(256) c2a_gate(const float* __restrict__ X,
                                                const float* __restrict__ Wg,
                                                const float* __restrict__ bg,
                                                float* __restrict__ TG) {
    int b = blockIdx.x >> 4, j = blockIdx.x & 15;
    int p0 = blockIdx.y * 512;
    __shared__ float w1[72], w2[72];
    if (threadIdx.x < 72) w1[threadIdx.x] = Wg[j * 72 + threadIdx.x];
    else if (threadIdx.x < 144) w2[threadIdx.x - 72] = Wg[(16 + j) * 72 + threadIdx.x - 72];
    __syncthreads();
    float b1 = bg[j], b2 = bg[16 + j];
    const float* x1p = X + ((size_t)b * CC + j * 8) * PP;
    const float* x2p = X + ((size_t)b * CC + (16 + j) * 8) * PP;
    for (int p = p0 + threadIdx.x; p < p0 + 512; p += 256) {
        int h = p >> 6, wq = p & 63;
        float t1 = b1, t2 = b2;
        for (int ci = 0; ci < 8; ci++) {
#pragma unroll
            for (int kh = 0; kh < 3; kh++) {
                int hh = h + kh - 1;
                if ((unsigned)hh >= (unsigned)HH) continue;
#pragma unroll
                for (int kw = 0; kw < 3; kw++) {
                    int wc = wq + kw - 1;
                    if ((unsigned)wc >= (unsigned)WW) continue;
                    float xv1 = x1p[(size_t)ci * PP + hh * WW + wc];
                    float xv2 = x2p[(size_t)ci * PP + hh * WW + wc];
                    t1 += xv1 * w1[ci * 9 + kh * 3 + kw];
                    t2 += xv2 * w2[ci * 9 + kh * 3 + kw];
                }
            }
        }
        TG[((size_t)b * 16 + j) * PP + p] = t1 * t2;
    }
}

// ---------------- att = (conv1x1(tg,c2b)+b)*gamma + attlin ----------------
__global__ void __launch_bounds__(256) att_mix(const float* __restrict__ TG,
                                               const float* __restrict__ c2bw,
                                               const float* __restrict__ c2bb,
                                               const float* __restrict__ attg,
                                               const float* __restrict__ ATTLIN,
                                               float* __restrict__ ATT) {
    int n = blockIdx.x;
    int b = blockIdx.z;
    int p0 = blockIdx.y * 1024;
    float wr[16];
#pragma unroll
    for (int q = 0; q < 16; q++) wr[q] = c2bw[n * 16 + q];
    float bb = c2bb[n], gam = attg[n];
    const float* tgb = TG + (size_t)b * 16 * PP;
    size_t base = ((size_t)b * NSET + n) * PP;
    for (int p = p0 + threadIdx.x; p < p0 + 1024; p += 256) {
        float s = bb;
#pragma unroll
        for (int q = 0; q < 16; q++) s += tgb[(size_t)q * PP + p] * wr[q];
        ATT[base + p] = s * gam + ATTLIN[base + p];
    }
}

// =========================================================================
// Dual-pass IKBA: both vertical and horizontal passes in one kernel.
// Block = (group, 2 H-rows = 128 pixels, batch). 128 threads = 4 warps.
// A [k=128][pix=128] stride 136 — filled ONCE, used by both GEMMs.
// B [n=56][k=128] stride 132 — filled twice (vertical w, then horiz w+bias).
// accV / accH both held in registers across the two mma loops.
// Epilogue: CsV/CsH in A alias; vertical matvec -> xh (smem, aliases B);
// horizontal matvec reads xh row-internal taps; OUT = s*ga1 + UF.
// =========================================================================
#define A_ST 136
#define B_ST 132
#define IKBA_SMEM_FLOATS (128 * A_ST + 56 * B_ST)

__global__ void __launch_bounds__(128) ikba_dual(const float* __restrict__ ATT,
                                                 const float* __restrict__ wcb,
                                                 const float* __restrict__ bcb,
                                                 const float* __restrict__ ga1,
                                                 const float* __restrict__ UF,
                                                 float* __restrict__ OUT) {
    extern __shared__ float sm[];
    uint32_t* Asu = (uint32_t*)sm;                // [128 k][A_ST]
    uint32_t* Bsu = (uint32_t*)(sm + 128 * A_ST); // [56 n][B_ST]
    float* CsV = sm;                              // alias: [128][57]
    float* CsH = sm + 7296;                       // alias: [128][57]
    float* xh = sm + 128 * A_ST;                  // alias of B: [4][128]

    int gr = blockIdx.x, h2 = blockIdx.y, b = blockIdx.z;
    int tid = threadIdx.x;
    int warp = tid >> 5, lane = tid & 31;
    int qr = lane >> 2, l4 = lane & 3;
    int m_base = warp << 5;

    // ---- A fill (once)
    {
        int quad = tid & 31, klane = tid >> 5;
        const float* ap = ATT + (size_t)b * NSET * PP + (size_t)h2 * 128 + quad * 4;
#pragma unroll 8
        for (int kk = 0; kk < 128; kk += 4) {
            int k = kk + klane;
            float4 v = *(const float4*)&ap[(size_t)k * PP];
            uint4 u = make_uint4(f2tf(v.x), f2tf(v.y), f2tf(v.z), f2tf(v.w));
            *(uint4*)&Asu[k * A_ST + quad * 4] = u;
        }
    }

    float accV[2][7][4], accH[2][7][4];
#pragma unroll
    for (int i = 0; i < 2; i++)
#pragma unroll
        for (int j = 0; j < 7; j++)
#pragma unroll
            for (int t = 0; t < 4; t++) { accV[i][j][t] = 0.f; accH[i][j][t] = 0.f; }

#pragma unroll
    for (int pass = 0; pass < 2; pass++) {
        // ---- B fill: rows 0..47 weights (halfoff = pass*3072)
        {
            const float* wp = wcb + pass * 3072 + gr * 48;
#pragma unroll
            for (int j = 0; j < 12; j++) {
                int l = j * 128 + tid;
                int k = l / 12, n4 = l - k * 12;
                float4 v = *(const float4*)&wp[(size_t)k * 6144 + n4 * 4];
                Bsu[(n4 * 4 + 0) * B_ST + k] = f2tf(v.x);
                Bsu[(n4 * 4 + 1) * B_ST + k] = f2tf(v.y);
                Bsu[(n4 * 4 + 2) * B_ST + k] = f2tf(v.z);
                Bsu[(n4 * 4 + 3) * B_ST + k] = f2tf(v.w);
            }
        }
        // ---- B rows 48..55: bias on horizontal pass, zero otherwise
#pragma unroll
        for (int j = 0; j < 8; j++) {
            int l = j * 128 + tid;
            int k = l >> 3, n = 48 + (l & 7);
            float v = 0.f;
            if (pass == 1 && n < 52) v = bcb[k * CC + gr * CGC + (n - 48)];
            Bsu[n * B_ST + k] = f2tf(v);
        }
        __syncthreads();

        for (int k0 = 0; k0 < 128; k0 += 8) {
            uint32_t a[2][4];
            int ka = (k0 + l4) * A_ST;
#pragma unroll
            for (int mt = 0; mt < 2; mt++) {
                int row = m_base + mt * 16 + qr;
                a[mt][0] = Asu[ka + row];
                a[mt][1] = Asu[ka + row + 8];
                a[mt][2] = Asu[ka + 4 * A_ST + row];
                a[mt][3] = Asu[ka + 4 * A_ST + row + 8];
            }
#pragma unroll
            for (int nt = 0; nt < 7; nt++) {
                int nr = (nt * 8 + qr) * B_ST + k0 + l4;
                uint32_t b0 = Bsu[nr];
                uint32_t b1 = Bsu[nr + 4];
#pragma unroll
                for (int mt = 0; mt < 2; mt++) {
                    if (pass == 0) MMA_TF32(accV[mt][nt], a[mt], b0, b1);
                    else           MMA_TF32(accH[mt][nt], a[mt], b0, b1);
                }
            }
        }
        __syncthreads();   // B reads done before refill / alias use
    }

    // ---- store both C tiles into A alias
#pragma unroll
    for (int mt = 0; mt < 2; mt++)
#pragma unroll
        for (int nt = 0; nt < 7; nt++) {
            int r = m_base + mt * 16 + qr;
            int cl = nt * 8 + 2 * l4;
            CsV[r * 57 + cl]           = accV[mt][nt][0];
            CsV[r * 57 + cl + 1]       = accV[mt][nt][1];
            CsV[(r + 8) * 57 + cl]     = accV[mt][nt][2];
            CsV[(r + 8) * 57 + cl + 1] = accV[mt][nt][3];
            CsH[r * 57 + cl]           = accH[mt][nt][0];
            CsH[r * 57 + cl + 1]       = accH[mt][nt][1];
            CsH[(r + 8) * 57 + cl]     = accH[mt][nt][2];
            CsH[(r + 8) * 57 + cl + 1] = accH[mt][nt][3];
        }
    __syncthreads();

    // ---- vertical matvec: thread = pixel -> xh[ci][pix] in smem
    int pix = tid, r0 = pix >> 6, cp = pix & 63;
    int h = h2 * 2 + r0;
    {
        float uf[12];
        size_t srcBase = (size_t)(b * CC + gr * CGC) * PP;
#pragma unroll
        for (int ci = 0; ci < 4; ci++)
#pragma unroll
            for (int tap = 0; tap < 3; tap++) {
                float v = 0.f;
                int hh = h + tap - 1;
                if ((unsigned)hh < (unsigned)HH)
                    v = UF[srcBase + (size_t)ci * PP + hh * WW + cp];
                uf[ci * 3 + tap] = v;
            }
        const float* cpr = &CsV[pix * 57];
#pragma unroll
        for (int oi = 0; oi < 4; oi++) {
            float s = 0.f;
#pragma unroll
            for (int j = 0; j < 12; j++) s += cpr[oi * 12 + j] * uf[j];
            xh[oi * 128 + pix] = s;
        }
    }
    __syncthreads();

    // ---- horizontal matvec: taps along W from smem xh; + bias; merge
    {
        float ufh[12];
#pragma unroll
        for (int ci = 0; ci < 4; ci++)
#pragma unroll
            for (int tap = 0; tap < 3; tap++) {
                float v = 0.f;
                int wc = cp + tap - 1;
                if ((unsigned)wc < (unsigned)WW)
                    v = xh[ci * 128 + pix + tap - 1];
                ufh[ci * 3 + tap] = v;
            }
        const float* cpr = &CsH[pix * 57];
        size_t obase = (size_t)(b * CC + gr * CGC) * PP + (size_t)h2 * 128 + pix;
#pragma unroll
        for (int oi = 0; oi < 4; oi++) {
            float s = cpr[48 + oi];
#pragma unroll
            for (int j = 0; j < 12; j++) s += cpr[oi * 12 + j] * ufh[j];
            size_t oidx = obase + (size_t)oi * PP;
            OUT[oidx] = s * ga1[gr * CGC + oi] + UF[oidx];
        }
    }
}

// ---------------- launch ----------------
extern "C" void kernel_launch(void* const* d_in, const int* in_sizes, int n_in,
                              void* d_out, int out_size) {
    const float* x       = (const float*)d_in[0];
    const float* dw1_w   = (const float*)d_in[1];
    const float* dw2_w   = (const float*)d_in[2];
    const float* proj_w  = (const float*)d_in[3];
    const float* lka0_w  = (const float*)d_in[4];
    const float* lkas_w  = (const float*)d_in[5];
    const float* lka1_w  = (const float*)d_in[6];
    const float* lka1_b  = (const float*)d_in[7];
    const float* sca_w   = (const float*)d_in[8];
    const float* sca_b   = (const float*)d_in[9];
    const float* c1a_w   = (const float*)d_in[10];
    const float* c1b_w   = (const float*)d_in[11];
    const float* c2a_w   = (const float*)d_in[12];
    const float* c2a_b   = (const float*)d_in[13];
    const float* c2b_w   = (const float*)d_in[14];
    const float* c2b_b   = (const float*)d_in[15];
    const float* c211_w  = (const float*)d_in[16];
    const float* c211_b  = (const float*)d_in[17];
    const float* w_cb    = (const float*)d_in[18];
    const float* b_cb    = (const float*)d_in[19];
    const float* attgam  = (const float*)d_in[20];
    const float* ga1     = (const float*)d_in[21];
    float* out = (float*)d_out;

    float *meanb, *scab, *ydw1, *yc1a, *attlin, *x1b, *ufb, *l1,
          *tg, *att, *x2b, *zb;
    cudaGetSymbolAddress((void**)&meanb, g_mean);
    cudaGetSymbolAddress((void**)&scab, g_sca);
    cudaGetSymbolAddress((void**)&ydw1, g_ydw1);
    cudaGetSymbolAddress((void**)&yc1a, g_yc1a);
    cudaGetSymbolAddress((void**)&attlin, g_attlin);
    cudaGetSymbolAddress((void**)&x1b, g_x1);
    cudaGetSymbolAddress((void**)&ufb, g_uf);
    cudaGetSymbolAddress((void**)&l1, g_l1);
    cudaGetSymbolAddress((void**)&tg, g_tg);
    cudaGetSymbolAddress((void**)&att, g_att);
    cudaGetSymbolAddress((void**)&x2b, g_x2);
    cudaGetSymbolAddress((void**)&zb, g_z);

    size_t gt_smem = GT_SMEM_FLOATS * sizeof(float);
    cudaFuncSetAttribute(gemm_tc<0>, cudaFuncAttributeMaxDynamicSharedMemorySize,
                         (int)gt_smem);
    cudaFuncSetAttribute(gemm_tc<1>, cudaFuncAttributeMaxDynamicSharedMemorySize,
                         (int)gt_smem);
    cudaFuncSetAttribute(gemm_tc<2>, cudaFuncAttributeMaxDynamicSharedMemorySize,
                         (int)gt_smem);

    // channel-attention branch
    meankern<<<BB * CC, 256>>>(x, meanb);
    scakern<<<BB, 256>>>(meanb, sca_w, sca_b, scab);

    // 1x1 convs from x, batched (dw1 -> ydw1, c1a -> yc1a, c211 -> attlin)
    gemm_tc<0><<<dim3(32, 10, BB), 256, gt_smem>>>(
        dw1_w, c1a_w, c211_w, c211_b, x, ydw1, yc1a, attlin,
        nullptr, nullptr, nullptr);

    // depthwise chains
    dw3x3_pair<<<BB * CC * 2, 256>>>(ydw1, dw2_w, x1b, yc1a, c1b_w, ufb);
    lka_chain<<<BB * CC, 256>>>(x, lka0_w, lkas_w, l1);

    // attention map
    c2a_gate<<<dim3(BB * 16, 8), 256>>>(x, c2a_w, c2a_b, tg);
    att_mix<<<dim3(NSET, 4, BB), 256>>>(tg, c2b_w, c2b_b, attgam, attlin, att);

    // dual-pass IKBA (single launch, A filled once, no xh global round-trip)
    size_t shmem = IKBA_SMEM_FLOATS * sizeof(float);
    cudaFuncSetAttribute(ikba_dual, cudaFuncAttributeMaxDynamicSharedMemorySize,
                         (int)shmem);
    ikba_dual<<<dim3(GG, 32, BB), 128, shmem>>>(att, w_cb, b_cb, ga1, ufb, x2b);

    // lka1 GEMM with fused elementwise merge: z = (W@l1+b)*x1*x2*sca
    gemm_tc<1><<<dim3(32, 4, BB), 256, gt_smem>>>(
        lka1_w, nullptr, nullptr, lka1_b, l1, zb, nullptr, nullptr,
        x1b, x2b, scab);

    // final projection
    gemm_tc<2><<<dim3(32, 4, BB), 256, gt_smem>>>(
        proj_w, nullptr, nullptr, nullptr, zb, out, nullptr, nullptr,
        nullptr, nullptr, nullptr);
}

// round 9
// speedup vs baseline: 2.2496x; 1.0667x over previous
#include <cuda_runtime.h>
#include <cuda_bf16.h>
#include <cstdint>
#include <cstddef>

// Problem constants
#define BB 2
#define CC 256
#define HH 64
#define WW 64
#define PP 4096          // H*W
#define NSET 128
#define GG 64            // groups
#define CGC 4            // channels per group

// ---------------- scratch (device globals; no allocs allowed) ----------------
__device__ float g_mean[BB * CC];
__device__ float g_sca[BB * CC];
__device__ float g_ydw1[BB * CC * PP];
__device__ float g_yc1a[BB * CC * PP];
__device__ float g_attlin[BB * NSET * PP];
__device__ float g_x1[BB * CC * PP];
__device__ float g_uf[BB * CC * PP];
__device__ float g_l1[BB * CC * PP];
__device__ float g_tg[BB * 16 * PP];
__device__ float g_att[BB * NSET * PP];
__device__ float g_x2[BB * CC * PP];
__device__ float g_z[BB * CC * PP];

__device__ __forceinline__ uint32_t f2tf(float f) {
    uint32_t r;
    asm("cvt.rna.tf32.f32 %0, %1;" : "=r"(r) : "f"(f));
    return r;
}

#define MMA_TF32(ACC, A, B0, B1)                                              \
    asm volatile(                                                             \
        "mma.sync.aligned.m16n8k8.row.col.f32.tf32.tf32.f32 "                 \
        "{%0,%1,%2,%3}, {%4,%5,%6,%7}, {%8,%9}, {%0,%1,%2,%3};"               \
        : "+f"((ACC)[0]), "+f"((ACC)[1]), "+f"((ACC)[2]), "+f"((ACC)[3])      \
        : "r"((A)[0]), "r"((A)[1]), "r"((A)[2]), "r"((A)[3]),                 \
          "r"(B0), "r"(B1))

// ---------------- mean over H,W per (b,c) ----------------
__global__ void __launch_bounds__(256) meankern(const float* __restrict__ X,
                                                float* __restrict__ M) {
    int bc = blockIdx.x;
    const float4* xp = (const float4*)(X + (size_t)bc * PP);
    float s = 0.f;
    for (int p = threadIdx.x; p < PP / 4; p += 256) {
        float4 v = xp[p];
        s += v.x + v.y + v.z + v.w;
    }
    __shared__ float red[256];
    red[threadIdx.x] = s;
    __syncthreads();
    for (int st = 128; st > 0; st >>= 1) {
        if (threadIdx.x < st) red[threadIdx.x] += red[threadIdx.x + st];
        __syncthreads();
    }
    if (threadIdx.x == 0) M[bc] = red[0] * (1.f / PP);
}

// ---------------- sca = 1x1 conv on the mean vector ----------------
__global__ void __launch_bounds__(256) scakern(const float* __restrict__ M,
                                               const float* __restrict__ Wsca,
                                               const float* __restrict__ Bsca,
                                               float* __restrict__ SCA) {
    int b = blockIdx.x;
    int o = threadIdx.x;
    __shared__ float m[CC];
    m[o] = M[b * CC + o];
    __syncthreads();
    float s = Bsca[o];
    const float* wr = Wsca + (size_t)o * CC;
    for (int c = 0; c < CC; c++) s += wr[c] * m[c];
    SCA[b * CC + o] = s;
}

// =========================================================================
// tf32x3 1x1-conv GEMM (proven R7). Tile 64M x 128N, 8 warps (2m x 4n).
// MODE 0: 3-way batch | MODE 1: lka merge epilogue | MODE 2: plain
// =========================================================================
#define GT_SMEM_FLOATS (2 * 2304 + 2 * 4352)

template <int MODE>
__global__ void __launch_bounds__(256) gemm_tc(
    const float* __restrict__ W0, const float* __restrict__ W1,
    const float* __restrict__ W2, const float* __restrict__ bias2,
    const float* __restrict__ X,
    float* __restrict__ Y0, float* __restrict__ Y1, float* __restrict__ Y2,
    const float* __restrict__ EX1, const float* __restrict__ EX2,
    const float* __restrict__ SCA) {
    extern __shared__ float smraw[];
    uint32_t* Ahi = (uint32_t*)smraw;              // [64][36]
    uint32_t* Alo = Ahi + 2304;
    uint32_t* Bhi = Alo + 2304;                    // [32][136]
    uint32_t* Blo = Bhi + 4352;

    int b = blockIdx.z, n0 = blockIdx.x << 7, my = blockIdx.y;
    const float* W;
    float* Y;
    const float* bias = nullptr;
    int m0, Msel;
    if (MODE == 0) {
        if (my < 4)      { W = W0; Y = Y0; m0 = my << 6; Msel = 256; }
        else if (my < 8) { W = W1; Y = Y1; m0 = (my - 4) << 6; Msel = 256; }
        else             { W = W2; Y = Y2; m0 = (my - 8) << 6; Msel = 128; bias = bias2; }
    } else {
        W = W0; Y = Y0; m0 = my << 6; Msel = 256; bias = bias2;
    }
    const float* Xb = X + (size_t)b * 256 * PP;
    int tid = threadIdx.x;
    int am = tid >> 2, akq = (tid & 3) << 3;
    int warp = tid >> 5, lane = tid & 31;
    int wm = warp & 1, wn = warp >> 1;
    int qr = lane >> 2, l4 = lane & 3;
    int m_warp = wm << 5, n_warp = wn << 5;
    float acc[2][4][4] = {};

    for (int k0 = 0; k0 < 256; k0 += 32) {
        {
            const float* wr = &W[(size_t)(m0 + am) * 256 + k0 + akq];
            float4 v0 = *(const float4*)wr;
            float4 v1 = *(const float4*)(wr + 4);
            uint4 h0, h1, q0, q1;
            h0.x = f2tf(v0.x); h0.y = f2tf(v0.y); h0.z = f2tf(v0.z); h0.w = f2tf(v0.w);
            h1.x = f2tf(v1.x); h1.y = f2tf(v1.y); h1.z = f2tf(v1.z); h1.w = f2tf(v1.w);
            q0.x = f2tf(v0.x - __uint_as_float(h0.x));
            q0.y = f2tf(v0.y - __uint_as_float(h0.y));
            q0.z = f2tf(v0.z - __uint_as_float(h0.z));
            q0.w = f2tf(v0.w - __uint_as_float(h0.w));
            q1.x = f2tf(v1.x - __uint_as_float(h1.x));
            q1.y = f2tf(v1.y - __uint_as_float(h1.y));
            q1.z = f2tf(v1.z - __uint_as_float(h1.z));
            q1.w = f2tf(v1.w - __uint_as_float(h1.w));
            int base = am * 36 + akq;
            *(uint4*)&Ahi[base] = h0;  *(uint4*)&Ahi[base + 4] = h1;
            *(uint4*)&Alo[base] = q0;  *(uint4*)&Alo[base + 4] = q1;
        }
#pragma unroll
        for (int j = 0; j < 4; j++) {
            int idx = tid + (j << 8);
            int kk = idx >> 5, nq = idx & 31;
            float4 v = *(const float4*)&Xb[(size_t)(k0 + kk) * PP + n0 + (nq << 2)];
            uint4 h, q;
            h.x = f2tf(v.x); h.y = f2tf(v.y); h.z = f2tf(v.z); h.w = f2tf(v.w);
            q.x = f2tf(v.x - __uint_as_float(h.x));
            q.y = f2tf(v.y - __uint_as_float(h.y));
            q.z = f2tf(v.z - __uint_as_float(h.z));
            q.w = f2tf(v.w - __uint_as_float(h.w));
            int base = kk * 136 + (nq << 2);
            *(uint4*)&Bhi[base] = h;
            *(uint4*)&Blo[base] = q;
        }
        __syncthreads();

#pragma unroll
        for (int ks = 0; ks < 32; ks += 8) {
            uint32_t ah[2][4], al[2][4];
#pragma unroll
            for (int mt = 0; mt < 2; mt++) {
                int r0 = (m_warp + mt * 16 + qr) * 36 + ks + l4;
                int r1 = r0 + 8 * 36;
                ah[mt][0] = Ahi[r0]; ah[mt][1] = Ahi[r1];
                ah[mt][2] = Ahi[r0 + 4]; ah[mt][3] = Ahi[r1 + 4];
                al[mt][0] = Alo[r0]; al[mt][1] = Alo[r1];
                al[mt][2] = Alo[r0 + 4]; al[mt][3] = Alo[r1 + 4];
            }
#pragma unroll
            for (int nt = 0; nt < 4; nt++) {
                int ncol = n_warp + nt * 8 + qr;
                int kb0 = (ks + l4) * 136 + ncol;
                int kb1 = kb0 + 4 * 136;
                uint32_t bh0 = Bhi[kb0], bh1 = Bhi[kb1];
                uint32_t bl0 = Blo[kb0], bl1 = Blo[kb1];
#pragma unroll
                for (int mt = 0; mt < 2; mt++) {
                    MMA_TF32(acc[mt][nt], ah[mt], bh0, bh1);
                    MMA_TF32(acc[mt][nt], ah[mt], bl0, bl1);
                    MMA_TF32(acc[mt][nt], al[mt], bh0, bh1);
                }
            }
        }
        __syncthreads();
    }

    float* Yb = Y + (size_t)b * Msel * PP;
#pragma unroll
    for (int mt = 0; mt < 2; mt++)
#pragma unroll
        for (int nt = 0; nt < 4; nt++) {
            int row = m_warp + mt * 16 + qr;
            int col = n_warp + nt * 8 + (l4 << 1);
#pragma unroll
            for (int rr = 0; rr < 2; rr++) {
                int rm = m0 + row + rr * 8;
                float c0 = acc[mt][nt][rr * 2], c1 = acc[mt][nt][rr * 2 + 1];
                size_t yidx = (size_t)(row + rr * 8 + m0) * PP + n0 + col;
                if (MODE == 1) {
                    float bb = bias[rm];
                    float sc = SCA[b * CC + rm];
                    size_t gidx = (size_t)b * CC * PP + (size_t)rm * PP + n0 + col;
                    float2 v1 = *(const float2*)&EX1[gidx];
                    float2 v2 = *(const float2*)&EX2[gidx];
                    float2 o = make_float2((c0 + bb) * v1.x * v2.x * sc,
                                           (c1 + bb) * v1.y * v2.y * sc);
                    *(float2*)&Yb[yidx] = o;
                } else {
                    float bb = (MODE == 0 && bias) ? bias[rm] : 0.f;
                    *(float2*)&Yb[yidx] = make_float2(c0 + bb, c1 + bb);
                }
            }
        }
}

// ---------------- depthwise conv body ----------------
template <int KS, int DIL, int PAD>
__device__ __forceinline__ void dw_conv_tile(const float* __restrict__ tile,
                                             const float* __restrict__ w,
                                             bool to_smem, float* smout,
                                             float* gout) {
    for (int p = threadIdx.x; p < PP; p += 256) {
        int h = p >> 6, ww = p & 63;
        float s = 0.f;
#pragma unroll
        for (int kh = 0; kh < KS; kh++) {
            int hh = h + DIL * kh - PAD;
            if ((unsigned)hh >= (unsigned)HH) continue;
#pragma unroll
            for (int kw = 0; kw < KS; kw++) {
                int wc = ww + DIL * kw - PAD;
                if ((unsigned)wc >= (unsigned)WW) continue;
                s += tile[hh * WW + wc] * w[kh * KS + kw];
            }
        }
        if (to_smem) smout[p] = s;
        else gout[p] = s;
    }
}

// all depthwise work in one launch:
//  blocks 0..1023: two independent 3x3 convs; blocks 1024..1535: LKA chain
__global__ void __launch_bounds__(256) dw_all(const float* __restrict__ X0,
                                              const float* __restrict__ W0,
                                              float* __restrict__ Y0,
                                              const float* __restrict__ X1,
                                              const float* __restrict__ W1,
                                              float* __restrict__ Y1,
                                              const float* __restrict__ XL,
                                              const float* __restrict__ W5,
                                              const float* __restrict__ W7,
                                              float* __restrict__ YL) {
    __shared__ float t0[PP];
    __shared__ float t1[PP];
    __shared__ float w[49 + 32];
    int id = blockIdx.x;
    int which = id >> 9, bc = id & 511;
    int c = bc & (CC - 1);
    if (which < 2) {
        const float* X = which ? X1 : X0;
        const float* Wd = which ? W1 : W0;
        float* Y = which ? Y1 : Y0;
        const float4* xp = (const float4*)(X + (size_t)bc * PP);
        for (int p = threadIdx.x; p < PP / 4; p += 256)
            ((float4*)t0)[p] = xp[p];
        if (threadIdx.x < 9) w[threadIdx.x] = Wd[c * 9 + threadIdx.x];
        __syncthreads();
        dw_conv_tile<3, 1, 1>(t0, w, false, nullptr, Y + (size_t)bc * PP);
    } else {
        const float4* xp = (const float4*)(XL + (size_t)bc * PP);
        for (int p = threadIdx.x; p < PP / 4; p += 256)
            ((float4*)t0)[p] = xp[p];
        if (threadIdx.x < 25) w[threadIdx.x] = W5[c * 25 + threadIdx.x];
        else if (threadIdx.x >= 32 && threadIdx.x < 81)
            w[threadIdx.x] = W7[c * 49 + threadIdx.x - 32];
        __syncthreads();
        dw_conv_tile<5, 1, 2>(t0, w, true, t1, nullptr);
        __syncthreads();
        dw_conv_tile<7, 3, 9>(t1, w + 32, false, nullptr, YL + (size_t)bc * PP);
    }
}

// ---------------- c2a grouped conv (groups=32) + SimpleGate ----------------
__global__ void __launch_bounds__(256) c2a_gate(const float* __restrict__ X,
                                                const float* __restrict__ Wg,
                                                const float* __restrict__ bg,
                                                float* __restrict__ TG) {
    int b = blockIdx.x >> 4, j = blockIdx.x & 15;
    int p0 = blockIdx.y * 512;
    __shared__ float w1[72], w2[72];
    if (threadIdx.x < 72) w1[threadIdx.x] = Wg[j * 72 + threadIdx.x];
    else if (threadIdx.x < 144) w2[threadIdx.x - 72] = Wg[(16 + j) * 72 + threadIdx.x - 72];
    __syncthreads();
    float b1 = bg[j], b2 = bg[16 + j];
    const float* x1p = X + ((size_t)b * CC + j * 8) * PP;
    const float* x2p = X + ((size_t)b * CC + (16 + j) * 8) * PP;
    for (int p = p0 + threadIdx.x; p < p0 + 512; p += 256) {
        int h = p >> 6, wq = p & 63;
        float t1 = b1, t2 = b2;
        for (int ci = 0; ci < 8; ci++) {
#pragma unroll
            for (int kh = 0; kh < 3; kh++) {
                int hh = h + kh - 1;
                if ((unsigned)hh >= (unsigned)HH) continue;
#pragma unroll
                for (int kw = 0; kw < 3; kw++) {
                    int wc = wq + kw - 1;
                    if ((unsigned)wc >= (unsigned)WW) continue;
                    float xv1 = x1p[(size_t)ci * PP + hh * WW + wc];
                    float xv2 = x2p[(size_t)ci * PP + hh * WW + wc];
                    t1 += xv1 * w1[ci * 9 + kh * 3 + kw];
                    t2 += xv2 * w2[ci * 9 + kh * 3 + kw];
                }
            }
        }
        TG[((size_t)b * 16 + j) * PP + p] = t1 * t2;
    }
}

// ---------------- att = (conv1x1(tg,c2b)+b)*gamma + attlin ----------------
__global__ void __launch_bounds__(256) att_mix(const float* __restrict__ TG,
                                               const float* __restrict__ c2bw,
                                               const float* __restrict__ c2bb,
                                               const float* __restrict__ attg,
                                               const float* __restrict__ ATTLIN,
                                               float* __restrict__ ATT) {
    int n = blockIdx.x;
    int b = blockIdx.z;
    int p0 = blockIdx.y * 1024;
    float wr[16];
#pragma unroll
    for (int q = 0; q < 16; q++) wr[q] = c2bw[n * 16 + q];
    float bb = c2bb[n], gam = attg[n];
    const float* tgb = TG + (size_t)b * 16 * PP;
    size_t base = ((size_t)b * NSET + n) * PP;
    for (int p = p0 + threadIdx.x; p < p0 + 1024; p += 256) {
        float s = bb;
#pragma unroll
        for (int q = 0; q < 16; q++) s += tgb[(size_t)q * PP + p] * wr[q];
        ATT[base + p] = s * gam + ATTLIN[base + p];
    }
}

// =========================================================================
// Dual-pass IKBA, k-chunked for 3 CTA/SM.
// Block = (group, 2 H-rows = 128 pixels, batch). 128 threads = 4 warps.
// Per k-chunk (64): A chunk [64k][136], Bv [56n][68], Bh [56n][68] resident
// together -> A fragments loaded once feed BOTH passes' mma.
// Epilogue identical to R8 (CsV/CsH alias, xh smem, fused two matvecs).
// =========================================================================
#define A_ST 136
#define B_ST 68
#define IK_BV (64 * A_ST)                 // 8704
#define IK_BH (IK_BV + 56 * B_ST)         // 12512
#define IKBA_SMEM_FLOATS (IK_BH + 56 * B_ST)   // 16320 floats = 65.3 KB

__global__ void __launch_bounds__(128, 3) ikba_dual(
        const float* __restrict__ ATT, const float* __restrict__ wcb,
        const float* __restrict__ bcb, const float* __restrict__ ga1,
        const float* __restrict__ UF, float* __restrict__ OUT) {
    extern __shared__ float sm[];
    uint32_t* Asu = (uint32_t*)sm;             // [64 k][A_ST]
    uint32_t* BsV = (uint32_t*)(sm + IK_BV);   // [56 n][B_ST]
    uint32_t* BsH = (uint32_t*)(sm + IK_BH);   // [56 n][B_ST]
    float* CsV = sm;                           // alias: [128][57] = 7296
    float* CsH = sm + 7296;                    // alias: [128][57]
    float* xh = sm + 14592;                    // alias: [4][128]

    int gr = blockIdx.x, h2 = blockIdx.y, b = blockIdx.z;
    int tid = threadIdx.x;
    int warp = tid >> 5, lane = tid & 31;
    int qr = lane >> 2, l4 = lane & 3;
    int m_base = warp << 5;

    float accV[2][7][4], accH[2][7][4];
#pragma unroll
    for (int i = 0; i < 2; i++)
#pragma unroll
        for (int j = 0; j < 7; j++)
#pragma unroll
            for (int t = 0; t < 4; t++) { accV[i][j][t] = 0.f; accH[i][j][t] = 0.f; }

#pragma unroll
    for (int kc = 0; kc < 2; kc++) {
        int kbase = kc * 64;
        // ---- A chunk fill
        {
            int quad = tid & 31, klane = tid >> 5;
            const float* ap = ATT + (size_t)b * NSET * PP
                            + (size_t)kbase * PP + (size_t)h2 * 128 + quad * 4;
#pragma unroll 8
            for (int kk = 0; kk < 64; kk += 4) {
                int k = kk + klane;
                float4 v = *(const float4*)&ap[(size_t)k * PP];
                uint4 u = make_uint4(f2tf(v.x), f2tf(v.y), f2tf(v.z), f2tf(v.w));
                *(uint4*)&Asu[k * A_ST + quad * 4] = u;
            }
        }
        // ---- B chunk fills (rows 0..47): vertical + horizontal weights
        {
            const float* wpv = wcb + gr * 48 + (size_t)kbase * 6144;
            const float* wph = wpv + 3072;
#pragma unroll
            for (int j = 0; j < 6; j++) {
                int l = j * 128 + tid;
                int k = l / 12, n4 = l - k * 12;
                float4 v = *(const float4*)&wpv[(size_t)k * 6144 + n4 * 4];
                BsV[(n4 * 4 + 0) * B_ST + k] = f2tf(v.x);
                BsV[(n4 * 4 + 1) * B_ST + k] = f2tf(v.y);
                BsV[(n4 * 4 + 2) * B_ST + k] = f2tf(v.z);
                BsV[(n4 * 4 + 3) * B_ST + k] = f2tf(v.w);
                float4 vh = *(const float4*)&wph[(size_t)k * 6144 + n4 * 4];
                BsH[(n4 * 4 + 0) * B_ST + k] = f2tf(vh.x);
                BsH[(n4 * 4 + 1) * B_ST + k] = f2tf(vh.y);
                BsH[(n4 * 4 + 2) * B_ST + k] = f2tf(vh.z);
                BsH[(n4 * 4 + 3) * B_ST + k] = f2tf(vh.w);
            }
        }
        // ---- B rows 48..55: zero (V) / bias+zero (H)
#pragma unroll
        for (int j = 0; j < 4; j++) {
            int l = j * 128 + tid;
            int k = l >> 3, n = 48 + (l & 7);
            BsV[n * B_ST + k] = 0u;
            float v = 0.f;
            if (n < 52) v = bcb[(kbase + k) * CC + gr * CGC + (n - 48)];
            BsH[n * B_ST + k] = f2tf(v);
        }
        __syncthreads();

        for (int k0 = 0; k0 < 64; k0 += 8) {
            uint32_t a[2][4];
            int ka = (k0 + l4) * A_ST;
#pragma unroll
            for (int mt = 0; mt < 2; mt++) {
                int row = m_base + mt * 16 + qr;
                a[mt][0] = Asu[ka + row];
                a[mt][1] = Asu[ka + row + 8];
                a[mt][2] = Asu[ka + 4 * A_ST + row];
                a[mt][3] = Asu[ka + 4 * A_ST + row + 8];
            }
#pragma unroll
            for (int nt = 0; nt < 7; nt++) {
                int nr = (nt * 8 + qr) * B_ST + k0 + l4;
                uint32_t bv0 = BsV[nr], bv1 = BsV[nr + 4];
                uint32_t bh0 = BsH[nr], bh1 = BsH[nr + 4];
#pragma unroll
                for (int mt = 0; mt < 2; mt++) {
                    MMA_TF32(accV[mt][nt], a[mt], bv0, bv1);
                    MMA_TF32(accH[mt][nt], a[mt], bh0, bh1);
                }
            }
        }
        __syncthreads();   // all smem reads done before refill / alias use
    }

    // ---- store both C tiles into alias
#pragma unroll
    for (int mt = 0; mt < 2; mt++)
#pragma unroll
        for (int nt = 0; nt < 7; nt++) {
            int r = m_base + mt * 16 + qr;
            int cl = nt * 8 + 2 * l4;
            CsV[r * 57 + cl]           = accV[mt][nt][0];
            CsV[r * 57 + cl + 1]       = accV[mt][nt][1];
            CsV[(r + 8) * 57 + cl]     = accV[mt][nt][2];
            CsV[(r + 8) * 57 + cl + 1] = accV[mt][nt][3];
            CsH[r * 57 + cl]           = accH[mt][nt][0];
            CsH[r * 57 + cl + 1]       = accH[mt][nt][1];
            CsH[(r + 8) * 57 + cl]     = accH[mt][nt][2];
            CsH[(r + 8) * 57 + cl + 1] = accH[mt][nt][3];
        }
    __syncthreads();

    // ---- vertical matvec: thread = pixel -> xh[ci][pix] in smem
    int pix = tid, r0 = pix >> 6, cp = pix & 63;
    int h = h2 * 2 + r0;
    {
        float uf[12];
        size_t srcBase = (size_t)(b * CC + gr * CGC) * PP;
#pragma unroll
        for (int ci = 0; ci < 4; ci++)
#pragma unroll
            for (int tap = 0; tap < 3; tap++) {
                float v = 0.f;
                int hh = h + tap - 1;
                if ((unsigned)hh < (unsigned)HH)
                    v = UF[srcBase + (size_t)ci * PP + hh * WW + cp];
                uf[ci * 3 + tap] = v;
            }
        const float* cpr = &CsV[pix * 57];
#pragma unroll
        for (int oi = 0; oi < 4; oi++) {
            float s = 0.f;
#pragma unroll
            for (int j = 0; j < 12; j++) s += cpr[oi * 12 + j] * uf[j];
            xh[oi * 128 + pix] = s;
        }
    }
    __syncthreads();

    // ---- horizontal matvec: taps along W from smem xh; + bias; merge
    {
        float ufh[12];
#pragma unroll
        for (int ci = 0; ci < 4; ci++)
#pragma unroll
            for (int tap = 0; tap < 3; tap++) {
                float v = 0.f;
                int wc = cp + tap - 1;
                if ((unsigned)wc < (unsigned)WW)
                    v = xh[ci * 128 + pix + tap - 1];
                ufh[ci * 3 + tap] = v;
            }
        const float* cpr = &CsH[pix * 57];
        size_t obase = (size_t)(b * CC + gr * CGC) * PP + (size_t)h2 * 128 + pix;
#pragma unroll
        for (int oi = 0; oi < 4; oi++) {
            float s = cpr[48 + oi];
#pragma unroll
            for (int j = 0; j < 12; j++) s += cpr[oi * 12 + j] * ufh[j];
            size_t oidx = obase + (size_t)oi * PP;
            OUT[oidx] = s * ga1[gr * CGC + oi] + UF[oidx];
        }
    }
}

// ---------------- launch ----------------
extern "C" void kernel_launch(void* const* d_in, const int* in_sizes, int n_in,
                              void* d_out, int out_size) {
    const float* x       = (const float*)d_in[0];
    const float* dw1_w   = (const float*)d_in[1];
    const float* dw2_w   = (const float*)d_in[2];
    const float* proj_w  = (const float*)d_in[3];
    const float* lka0_w  = (const float*)d_in[4];
    const float* lkas_w  = (const float*)d_in[5];
    const float* lka1_w  = (const float*)d_in[6];
    const float* lka1_b  = (const float*)d_in[7];
    const float* sca_w   = (const float*)d_in[8];
    const float* sca_b   = (const float*)d_in[9];
    const float* c1a_w   = (const float*)d_in[10];
    const float* c1b_w   = (const float*)d_in[11];
    const float* c2a_w   = (const float*)d_in[12];
    const float* c2a_b   = (const float*)d_in[13];
    const float* c2b_w   = (const float*)d_in[14];
    const float* c2b_b   = (const float*)d_in[15];
    const float* c211_w  = (const float*)d_in[16];
    const float* c211_b  = (const float*)d_in[17];
    const float* w_cb    = (const float*)d_in[18];
    const float* b_cb    = (const float*)d_in[19];
    const float* attgam  = (const float*)d_in[20];
    const float* ga1     = (const float*)d_in[21];
    float* out = (float*)d_out;

    float *meanb, *scab, *ydw1, *yc1a, *attlin, *x1b, *ufb, *l1,
          *tg, *att, *x2b, *zb;
    cudaGetSymbolAddress((void**)&meanb, g_mean);
    cudaGetSymbolAddress((void**)&scab, g_sca);
    cudaGetSymbolAddress((void**)&ydw1, g_ydw1);
    cudaGetSymbolAddress((void**)&yc1a, g_yc1a);
    cudaGetSymbolAddress((void**)&attlin, g_attlin);
    cudaGetSymbolAddress((void**)&x1b, g_x1);
    cudaGetSymbolAddress((void**)&ufb, g_uf);
    cudaGetSymbolAddress((void**)&l1, g_l1);
    cudaGetSymbolAddress((void**)&tg, g_tg);
    cudaGetSymbolAddress((void**)&att, g_att);
    cudaGetSymbolAddress((void**)&x2b, g_x2);
    cudaGetSymbolAddress((void**)&zb, g_z);

    size_t gt_smem = GT_SMEM_FLOATS * sizeof(float);
    cudaFuncSetAttribute(gemm_tc<0>, cudaFuncAttributeMaxDynamicSharedMemorySize,
                         (int)gt_smem);
    cudaFuncSetAttribute(gemm_tc<1>, cudaFuncAttributeMaxDynamicSharedMemorySize,
                         (int)gt_smem);
    cudaFuncSetAttribute(gemm_tc<2>, cudaFuncAttributeMaxDynamicSharedMemorySize,
                         (int)gt_smem);

    // channel-attention branch
    meankern<<<BB * CC, 256>>>(x, meanb);
    scakern<<<BB, 256>>>(meanb, sca_w, sca_b, scab);

    // 1x1 convs from x, batched (dw1 -> ydw1, c1a -> yc1a, c211 -> attlin)
    gemm_tc<0><<<dim3(32, 10, BB), 256, gt_smem>>>(
        dw1_w, c1a_w, c211_w, c211_b, x, ydw1, yc1a, attlin,
        nullptr, nullptr, nullptr);

    // all depthwise work in one launch (two 3x3 + LKA chain)
    dw_all<<<BB * CC * 3, 256>>>(ydw1, dw2_w, x1b, yc1a, c1b_w, ufb,
                                 x, lka0_w, lkas_w, l1);

    // attention map
    c2a_gate<<<dim3(BB * 16, 8), 256>>>(x, c2a_w, c2a_b, tg);
    att_mix<<<dim3(NSET, 4, BB), 256>>>(tg, c2b_w, c2b_b, attgam, attlin, att);

    // dual-pass IKBA (k-chunked, 3 CTA/SM)
    size_t shmem = IKBA_SMEM_FLOATS * sizeof(float);
    cudaFuncSetAttribute(ikba_dual, cudaFuncAttributeMaxDynamicSharedMemorySize,
                         (int)shmem);
    ikba_dual<<<dim3(GG, 32, BB), 128, shmem>>>(att, w_cb, b_cb, ga1, ufb, x2b);

    // lka1 GEMM with fused elementwise merge: z = (W@l1+b)*x1*x2*sca
    gemm_tc<1><<<dim3(32, 4, BB), 256, gt_smem>>>(
        lka1_w, nullptr, nullptr, lka1_b, l1, zb, nullptr, nullptr,
        x1b, x2b, scab);

    // final projection
    gemm_tc<2><<<dim3(32, 4, BB), 256, gt_smem>>>(
        proj_w, nullptr, nullptr, nullptr, zb, out, nullptr, nullptr,
        nullptr, nullptr, nullptr);
}

// round 10
// speedup vs baseline: 2.3444x; 1.0422x over previous
#include <cuda_runtime.h>
#include <cuda_bf16.h>
#include <cstdint>
#include <cstddef>

// Problem constants
#define BB 2
#define CC 256
#define HH 64
#define WW 64
#define PP 4096          // H*W
#define NSET 128
#define GG 64            // groups
#define CGC 4            // channels per group

// ---------------- scratch (device globals; no allocs allowed) ----------------
__device__ float g_mean[BB * CC];
__device__ float g_sca[BB * CC];
__device__ float g_ydw1[BB * CC * PP];
__device__ float g_yc1a[BB * CC * PP];
__device__ float g_attlin[BB * NSET * PP];
__device__ float g_x1[BB * CC * PP];
__device__ float g_uf[BB * CC * PP];
__device__ float g_l1[BB * CC * PP];
__device__ float g_tg[BB * 16 * PP];
__device__ float g_att[BB * NSET * PP];
__device__ float g_x2[BB * CC * PP];
__device__ float g_z[BB * CC * PP];

__device__ __forceinline__ uint32_t f2tf(float f) {
    uint32_t r;
    asm("cvt.rna.tf32.f32 %0, %1;" : "=r"(r) : "f"(f));
    return r;
}

#define MMA_TF32(ACC, A, B0, B1)                                              \
    asm volatile(                                                             \
        "mma.sync.aligned.m16n8k8.row.col.f32.tf32.tf32.f32 "                 \
        "{%0,%1,%2,%3}, {%4,%5,%6,%7}, {%8,%9}, {%0,%1,%2,%3};"               \
        : "+f"((ACC)[0]), "+f"((ACC)[1]), "+f"((ACC)[2]), "+f"((ACC)[3])      \
        : "r"((A)[0]), "r"((A)[1]), "r"((A)[2]), "r"((A)[3]),                 \
          "r"(B0), "r"(B1))

// ---------------- mean over H,W per (b,c) ----------------
__global__ void __launch_bounds__(256) meankern(const float* __restrict__ X,
                                                float* __restrict__ M) {
    int bc = blockIdx.x;
    const float4* xp = (const float4*)(X + (size_t)bc * PP);
    float s = 0.f;
    for (int p = threadIdx.x; p < PP / 4; p += 256) {
        float4 v = xp[p];
        s += v.x + v.y + v.z + v.w;
    }
    __shared__ float red[256];
    red[threadIdx.x] = s;
    __syncthreads();
    for (int st = 128; st > 0; st >>= 1) {
        if (threadIdx.x < st) red[threadIdx.x] += red[threadIdx.x + st];
        __syncthreads();
    }
    if (threadIdx.x == 0) M[bc] = red[0] * (1.f / PP);
}

// ---------------- sca = 1x1 conv on the mean vector ----------------
__global__ void __launch_bounds__(256) scakern(const float* __restrict__ M,
                                               const float* __restrict__ Wsca,
                                               const float* __restrict__ Bsca,
                                               float* __restrict__ SCA) {
    int b = blockIdx.x;
    int o = threadIdx.x;
    __shared__ float m[CC];
    m[o] = M[b * CC + o];
    __syncthreads();
    float s = Bsca[o];
    const float* wr = Wsca + (size_t)o * CC;
    for (int c = 0; c < CC; c++) s += wr[c] * m[c];
    SCA[b * CC + o] = s;
}

// =========================================================================
// tf32x3 1x1-conv GEMM (proven). Tile 64M x 128N, 8 warps (2m x 4n).
// MODE 0: 3-way batch | MODE 1: lka merge epilogue | MODE 2: plain
// =========================================================================
#define GT_SMEM_FLOATS (2 * 2304 + 2 * 4352)

template <int MODE>
__global__ void __launch_bounds__(256) gemm_tc(
    const float* __restrict__ W0, const float* __restrict__ W1,
    const float* __restrict__ W2, const float* __restrict__ bias2,
    const float* __restrict__ X,
    float* __restrict__ Y0, float* __restrict__ Y1, float* __restrict__ Y2,
    const float* __restrict__ EX1, const float* __restrict__ EX2,
    const float* __restrict__ SCA) {
    extern __shared__ float smraw[];
    uint32_t* Ahi = (uint32_t*)smraw;              // [64][36]
    uint32_t* Alo = Ahi + 2304;
    uint32_t* Bhi = Alo + 2304;                    // [32][136]
    uint32_t* Blo = Bhi + 4352;

    int b = blockIdx.z, n0 = blockIdx.x << 7, my = blockIdx.y;
    const float* W;
    float* Y;
    const float* bias = nullptr;
    int m0, Msel;
    if (MODE == 0) {
        if (my < 4)      { W = W0; Y = Y0; m0 = my << 6; Msel = 256; }
        else if (my < 8) { W = W1; Y = Y1; m0 = (my - 4) << 6; Msel = 256; }
        else             { W = W2; Y = Y2; m0 = (my - 8) << 6; Msel = 128; bias = bias2; }
    } else {
        W = W0; Y = Y0; m0 = my << 6; Msel = 256; bias = bias2;
    }
    const float* Xb = X + (size_t)b * 256 * PP;
    int tid = threadIdx.x;
    int am = tid >> 2, akq = (tid & 3) << 3;
    int warp = tid >> 5, lane = tid & 31;
    int wm = warp & 1, wn = warp >> 1;
    int qr = lane >> 2, l4 = lane & 3;
    int m_warp = wm << 5, n_warp = wn << 5;
    float acc[2][4][4] = {};

    for (int k0 = 0; k0 < 256; k0 += 32) {
        {
            const float* wr = &W[(size_t)(m0 + am) * 256 + k0 + akq];
            float4 v0 = *(const float4*)wr;
            float4 v1 = *(const float4*)(wr + 4);
            uint4 h0, h1, q0, q1;
            h0.x = f2tf(v0.x); h0.y = f2tf(v0.y); h0.z = f2tf(v0.z); h0.w = f2tf(v0.w);
            h1.x = f2tf(v1.x); h1.y = f2tf(v1.y); h1.z = f2tf(v1.z); h1.w = f2tf(v1.w);
            q0.x = f2tf(v0.x - __uint_as_float(h0.x));
            q0.y = f2tf(v0.y - __uint_as_float(h0.y));
            q0.z = f2tf(v0.z - __uint_as_float(h0.z));
            q0.w = f2tf(v0.w - __uint_as_float(h0.w));
            q1.x = f2tf(v1.x - __uint_as_float(h1.x));
            q1.y = f2tf(v1.y - __uint_as_float(h1.y));
            q1.z = f2tf(v1.z - __uint_as_float(h1.z));
            q1.w = f2tf(v1.w - __uint_as_float(h1.w));
            int base = am * 36 + akq;
            *(uint4*)&Ahi[base] = h0;  *(uint4*)&Ahi[base + 4] = h1;
            *(uint4*)&Alo[base] = q0;  *(uint4*)&Alo[base + 4] = q1;
        }
#pragma unroll
        for (int j = 0; j < 4; j++) {
            int idx = tid + (j << 8);
            int kk = idx >> 5, nq = idx & 31;
            float4 v = *(const float4*)&Xb[(size_t)(k0 + kk) * PP + n0 + (nq << 2)];
            uint4 h, q;
            h.x = f2tf(v.x); h.y = f2tf(v.y); h.z = f2tf(v.z); h.w = f2tf(v.w);
            q.x = f2tf(v.x - __uint_as_float(h.x));
            q.y = f2tf(v.y - __uint_as_float(h.y));
            q.z = f2tf(v.z - __uint_as_float(h.z));
            q.w = f2tf(v.w - __uint_as_float(h.w));
            int base = kk * 136 + (nq << 2);
            *(uint4*)&Bhi[base] = h;
            *(uint4*)&Blo[base] = q;
        }
        __syncthreads();

#pragma unroll
        for (int ks = 0; ks < 32; ks += 8) {
            uint32_t ah[2][4], al[2][4];
#pragma unroll
            for (int mt = 0; mt < 2; mt++) {
                int r0 = (m_warp + mt * 16 + qr) * 36 + ks + l4;
                int r1 = r0 + 8 * 36;
                ah[mt][0] = Ahi[r0]; ah[mt][1] = Ahi[r1];
                ah[mt][2] = Ahi[r0 + 4]; ah[mt][3] = Ahi[r1 + 4];
                al[mt][0] = Alo[r0]; al[mt][1] = Alo[r1];
                al[mt][2] = Alo[r0 + 4]; al[mt][3] = Alo[r1 + 4];
            }
#pragma unroll
            for (int nt = 0; nt < 4; nt++) {
                int ncol = n_warp + nt * 8 + qr;
                int kb0 = (ks + l4) * 136 + ncol;
                int kb1 = kb0 + 4 * 136;
                uint32_t bh0 = Bhi[kb0], bh1 = Bhi[kb1];
                uint32_t bl0 = Blo[kb0], bl1 = Blo[kb1];
#pragma unroll
                for (int mt = 0; mt < 2; mt++) {
                    MMA_TF32(acc[mt][nt], ah[mt], bh0, bh1);
                    MMA_TF32(acc[mt][nt], ah[mt], bl0, bl1);
                    MMA_TF32(acc[mt][nt], al[mt], bh0, bh1);
                }
            }
        }
        __syncthreads();
    }

    float* Yb = Y + (size_t)b * Msel * PP;
#pragma unroll
    for (int mt = 0; mt < 2; mt++)
#pragma unroll
        for (int nt = 0; nt < 4; nt++) {
            int row = m_warp + mt * 16 + qr;
            int col = n_warp + nt * 8 + (l4 << 1);
#pragma unroll
            for (int rr = 0; rr < 2; rr++) {
                int rm = m0 + row + rr * 8;
                float c0 = acc[mt][nt][rr * 2], c1 = acc[mt][nt][rr * 2 + 1];
                size_t yidx = (size_t)(row + rr * 8 + m0) * PP + n0 + col;
                if (MODE == 1) {
                    float bb = bias[rm];
                    float sc = SCA[b * CC + rm];
                    size_t gidx = (size_t)b * CC * PP + (size_t)rm * PP + n0 + col;
                    float2 v1 = *(const float2*)&EX1[gidx];
                    float2 v2 = *(const float2*)&EX2[gidx];
                    float2 o = make_float2((c0 + bb) * v1.x * v2.x * sc,
                                           (c1 + bb) * v1.y * v2.y * sc);
                    *(float2*)&Yb[yidx] = o;
                } else {
                    float bb = (MODE == 0 && bias) ? bias[rm] : 0.f;
                    *(float2*)&Yb[yidx] = make_float2(c0 + bb, c1 + bb);
                }
            }
        }
}

// =========================================================================
// Depthwise convs with zero-padded smem tiles (no bounds predicates).
// =========================================================================
// two independent 3x3 depthwise convs in one launch; tile [66][68], halo 1
__global__ void __launch_bounds__(256) dw3x3_pair(const float* __restrict__ X0,
                                                  const float* __restrict__ W0,
                                                  float* __restrict__ Y0,
                                                  const float* __restrict__ X1,
                                                  const float* __restrict__ W1,
                                                  float* __restrict__ Y1) {
    __shared__ float t[66 * 68];
    __shared__ float w[9];
    int id = blockIdx.x;
    int which = id >> 9, bc = id & 511;
    int c = bc & (CC - 1);
    const float* X = which ? X1 : X0;
    const float* Wd = which ? W1 : W0;
    float* Y = which ? Y1 : Y0;
    for (int i = threadIdx.x; i < (66 * 68) / 4; i += 256)
        ((float4*)t)[i] = make_float4(0.f, 0.f, 0.f, 0.f);
    if (threadIdx.x < 9) w[threadIdx.x] = Wd[c * 9 + threadIdx.x];
    __syncthreads();
    const float* xp = X + (size_t)bc * PP;
    for (int p = threadIdx.x; p < PP; p += 256) {
        int h = p >> 6, ww = p & 63;
        t[(h + 1) * 68 + ww + 1] = xp[p];
    }
    __syncthreads();
    float* yp = Y + (size_t)bc * PP;
    for (int p = threadIdx.x; p < PP; p += 256) {
        int h = p >> 6, ww = p & 63;
        const float* base = &t[h * 68 + ww];
        float s = 0.f;
#pragma unroll
        for (int kh = 0; kh < 3; kh++)
#pragma unroll
            for (int kw = 0; kw < 3; kw++)
                s += base[kh * 68 + kw] * w[kh * 3 + kw];
        yp[p] = s;
    }
}

// fused LKA depthwise chain with padded tiles:
//  t0p [68][68] halo 2 (5x5), t1p [82][84] halo 9 (7x7 dil3)
__global__ void __launch_bounds__(256) lka_chain(const float* __restrict__ X,
                                                 const float* __restrict__ W5,
                                                 const float* __restrict__ W7,
                                                 float* __restrict__ OUT) {
    __shared__ float t0p[68 * 68];
    __shared__ float t1p[82 * 84];
    __shared__ float w5[25], w7[49];
    int bc = blockIdx.x;
    int c = bc & (CC - 1);
    for (int i = threadIdx.x; i < (68 * 68) / 4; i += 256)
        ((float4*)t0p)[i] = make_float4(0.f, 0.f, 0.f, 0.f);
    for (int i = threadIdx.x; i < (82 * 84) / 4; i += 256)
        ((float4*)t1p)[i] = make_float4(0.f, 0.f, 0.f, 0.f);
    if (threadIdx.x < 25) w5[threadIdx.x] = W5[c * 25 + threadIdx.x];
    else if (threadIdx.x >= 32 && threadIdx.x < 81)
        w7[threadIdx.x - 32] = W7[c * 49 + threadIdx.x - 32];
    __syncthreads();
    const float* xp = X + (size_t)bc * PP;
    for (int p = threadIdx.x; p < PP; p += 256) {
        int h = p >> 6, ww = p & 63;
        t0p[(h + 2) * 68 + ww + 2] = xp[p];
    }
    __syncthreads();
    // 5x5 pad2: output (h,w) reads t0p[(h+kh)*68 + w+kw]
    for (int p = threadIdx.x; p < PP; p += 256) {
        int h = p >> 6, ww = p & 63;
        const float* base = &t0p[h * 68 + ww];
        float s = 0.f;
#pragma unroll
        for (int kh = 0; kh < 5; kh++)
#pragma unroll
            for (int kw = 0; kw < 5; kw++)
                s += base[kh * 68 + kw] * w5[kh * 5 + kw];
        t1p[(h + 9) * 84 + ww + 9] = s;
    }
    __syncthreads();
    // 7x7 dil3 pad9: output (h,w) reads t1p[(h+3kh)*84 + w+3kw]
    float* yp = OUT + (size_t)bc * PP;
    for (int p = threadIdx.x; p < PP; p += 256) {
        int h = p >> 6, ww = p & 63;
        const float* base = &t1p[h * 84 + ww];
        float s = 0.f;
#pragma unroll
        for (int kh = 0; kh < 7; kh++)
#pragma unroll
            for (int kw = 0; kw < 7; kw++)
                s += base[kh * 3 * 84 + kw * 3] * w7[kh * 7 + kw];
        yp[p] = s;
    }
}

// ---------------- c2a grouped conv (groups=32) + SimpleGate ----------------
__global__ void __launch_bounds__(256) c2a_gate(const float* __restrict__ X,
                                                const float* __restrict__ Wg,
                                                const float* __restrict__ bg,
                                                float* __restrict__ TG) {
    int b = blockIdx.x >> 4, j = blockIdx.x & 15;
    int p0 = blockIdx.y * 512;
    __shared__ float w1[72], w2[72];
    if (threadIdx.x < 72) w1[threadIdx.x] = Wg[j * 72 + threadIdx.x];
    else if (threadIdx.x < 144) w2[threadIdx.x - 72] = Wg[(16 + j) * 72 + threadIdx.x - 72];
    __syncthreads();
    float b1 = bg[j], b2 = bg[16 + j];
    const float* x1p = X + ((size_t)b * CC + j * 8) * PP;
    const float* x2p = X + ((size_t)b * CC + (16 + j) * 8) * PP;
    for (int p = p0 + threadIdx.x; p < p0 + 512; p += 256) {
        int h = p >> 6, wq = p & 63;
        float t1 = b1, t2 = b2;
        for (int ci = 0; ci < 8; ci++) {
#pragma unroll
            for (int kh = 0; kh < 3; kh++) {
                int hh = h + kh - 1;
                if ((unsigned)hh >= (unsigned)HH) continue;
#pragma unroll
                for (int kw = 0; kw < 3; kw++) {
                    int wc = wq + kw - 1;
                    if ((unsigned)wc >= (unsigned)WW) continue;
                    float xv1 = x1p[(size_t)ci * PP + hh * WW + wc];
                    float xv2 = x2p[(size_t)ci * PP + hh * WW + wc];
                    t1 += xv1 * w1[ci * 9 + kh * 3 + kw];
                    t2 += xv2 * w2[ci * 9 + kh * 3 + kw];
                }
            }
        }
        TG[((size_t)b * 16 + j) * PP + p] = t1 * t2;
    }
}

// ---------------- att = (conv1x1(tg,c2b)+b)*gamma + attlin ----------------
__global__ void __launch_bounds__(256) att_mix(const float* __restrict__ TG,
                                               const float* __restrict__ c2bw,
                                               const float* __restrict__ c2bb,
                                               const float* __restrict__ attg,
                                               const float* __restrict__ ATTLIN,
                                               float* __restrict__ ATT) {
    int n = blockIdx.x;
    int b = blockIdx.z;
    int p0 = blockIdx.y * 1024;
    float wr[16];
#pragma unroll
    for (int q = 0; q < 16; q++) wr[q] = c2bw[n * 16 + q];
    float bb = c2bb[n], gam = attg[n];
    const float* tgb = TG + (size_t)b * 16 * PP;
    size_t base = ((size_t)b * NSET + n) * PP;
    for (int p = p0 + threadIdx.x; p < p0 + 1024; p += 256) {
        float s = bb;
#pragma unroll
        for (int q = 0; q < 16; q++) s += tgb[(size_t)q * PP + p] * wr[q];
        ATT[base + p] = s * gam + ATTLIN[base + p];
    }
}

// =========================================================================
// Dual-pass IKBA, k-chunked for 3 CTA/SM (proven R9).
// =========================================================================
#define A_ST 136
#define B_ST 68
#define IK_BV (64 * A_ST)                 // 8704
#define IK_BH (IK_BV + 56 * B_ST)         // 12512
#define IKBA_SMEM_FLOATS (IK_BH + 56 * B_ST)   // 16320 floats = 65.3 KB

__global__ void __launch_bounds__(128, 3) ikba_dual(
        const float* __restrict__ ATT, const float* __restrict__ wcb,
        const float* __restrict__ bcb, const float* __restrict__ ga1,
        const float* __restrict__ UF, float* __restrict__ OUT) {
    extern __shared__ float sm[];
    uint32_t* Asu = (uint32_t*)sm;             // [64 k][A_ST]
    uint32_t* BsV = (uint32_t*)(sm + IK_BV);   // [56 n][B_ST]
    uint32_t* BsH = (uint32_t*)(sm + IK_BH);   // [56 n][B_ST]
    float* CsV = sm;                           // alias: [128][57] = 7296
    float* CsH = sm + 7296;                    // alias: [128][57]
    float* xh = sm + 14592;                    // alias: [4][128]

    int gr = blockIdx.x, h2 = blockIdx.y, b = blockIdx.z;
    int tid = threadIdx.x;
    int warp = tid >> 5, lane = tid & 31;
    int qr = lane >> 2, l4 = lane & 3;
    int m_base = warp << 5;

    float accV[2][7][4], accH[2][7][4];
#pragma unroll
    for (int i = 0; i < 2; i++)
#pragma unroll
        for (int j = 0; j < 7; j++)
#pragma unroll
            for (int t = 0; t < 4; t++) { accV[i][j][t] = 0.f; accH[i][j][t] = 0.f; }

#pragma unroll
    for (int kc = 0; kc < 2; kc++) {
        int kbase = kc * 64;
        {
            int quad = tid & 31, klane = tid >> 5;
            const float* ap = ATT + (size_t)b * NSET * PP
                            + (size_t)kbase * PP + (size_t)h2 * 128 + quad * 4;
#pragma unroll 8
            for (int kk = 0; kk < 64; kk += 4) {
                int k = kk + klane;
                float4 v = *(const float4*)&ap[(size_t)k * PP];
                uint4 u = make_uint4(f2tf(v.x), f2tf(v.y), f2tf(v.z), f2tf(v.w));
                *(uint4*)&Asu[k * A_ST + quad * 4] = u;
            }
        }
        {
            const float* wpv = wcb + gr * 48 + (size_t)kbase * 6144;
            const float* wph = wpv + 3072;
#pragma unroll
            for (int j = 0; j < 6; j++) {
                int l = j * 128 + tid;
                int k = l / 12, n4 = l - k * 12;
                float4 v = *(const float4*)&wpv[(size_t)k * 6144 + n4 * 4];
                BsV[(n4 * 4 + 0) * B_ST + k] = f2tf(v.x);
                BsV[(n4 * 4 + 1) * B_ST + k] = f2tf(v.y);
                BsV[(n4 * 4 + 2) * B_ST + k] = f2tf(v.z);
                BsV[(n4 * 4 + 3) * B_ST + k] = f2tf(v.w);
                float4 vh = *(const float4*)&wph[(size_t)k * 6144 + n4 * 4];
                BsH[(n4 * 4 + 0) * B_ST + k] = f2tf(vh.x);
                BsH[(n4 * 4 + 1) * B_ST + k] = f2tf(vh.y);
                BsH[(n4 * 4 + 2) * B_ST + k] = f2tf(vh.z);
                BsH[(n4 * 4 + 3) * B_ST + k] = f2tf(vh.w);
            }
        }
#pragma unroll
        for (int j = 0; j < 4; j++) {
            int l = j * 128 + tid;
            int k = l >> 3, n = 48 + (l & 7);
            BsV[n * B_ST + k] = 0u;
            float v = 0.f;
            if (n < 52) v = bcb[(kbase + k) * CC + gr * CGC + (n - 48)];
            BsH[n * B_ST + k] = f2tf(v);
        }
        __syncthreads();

        for (int k0 = 0; k0 < 64; k0 += 8) {
            uint32_t a[2][4];
            int ka = (k0 + l4) * A_ST;
#pragma unroll
            for (int mt = 0; mt < 2; mt++) {
                int row = m_base + mt * 16 + qr;
                a[mt][0] = Asu[ka + row];
                a[mt][1] = Asu[ka + row + 8];
                a[mt][2] = Asu[ka + 4 * A_ST + row];
                a[mt][3] = Asu[ka + 4 * A_ST + row + 8];
            }
#pragma unroll
            for (int nt = 0; nt < 7; nt++) {
                int nr = (nt * 8 + qr) * B_ST + k0 + l4;
                uint32_t bv0 = BsV[nr], bv1 = BsV[nr + 4];
                uint32_t bh0 = BsH[nr], bh1 = BsH[nr + 4];
#pragma unroll
                for (int mt = 0; mt < 2; mt++) {
                    MMA_TF32(accV[mt][nt], a[mt], bv0, bv1);
                    MMA_TF32(accH[mt][nt], a[mt], bh0, bh1);
                }
            }
        }
        __syncthreads();
    }

#pragma unroll
    for (int mt = 0; mt < 2; mt++)
#pragma unroll
        for (int nt = 0; nt < 7; nt++) {
            int r = m_base + mt * 16 + qr;
            int cl = nt * 8 + 2 * l4;
            CsV[r * 57 + cl]           = accV[mt][nt][0];
            CsV[r * 57 + cl + 1]       = accV[mt][nt][1];
            CsV[(r + 8) * 57 + cl]     = accV[mt][nt][2];
            CsV[(r + 8) * 57 + cl + 1] = accV[mt][nt][3];
            CsH[r * 57 + cl]           = accH[mt][nt][0];
            CsH[r * 57 + cl + 1]       = accH[mt][nt][1];
            CsH[(r + 8) * 57 + cl]     = accH[mt][nt][2];
            CsH[(r + 8) * 57 + cl + 1] = accH[mt][nt][3];
        }
    __syncthreads();

    int pix = tid, r0 = pix >> 6, cp = pix & 63;
    int h = h2 * 2 + r0;
    {
        float uf[12];
        size_t srcBase = (size_t)(b * CC + gr * CGC) * PP;
#pragma unroll
        for (int ci = 0; ci < 4; ci++)
#pragma unroll
            for (int tap = 0; tap < 3; tap++) {
                float v = 0.f;
                int hh = h + tap - 1;
                if ((unsigned)hh < (unsigned)HH)
                    v = UF[srcBase + (size_t)ci * PP + hh * WW + cp];
                uf[ci * 3 + tap] = v;
            }
        const float* cpr = &CsV[pix * 57];
#pragma unroll
        for (int oi = 0; oi < 4; oi++) {
            float s = 0.f;
#pragma unroll
            for (int j = 0; j < 12; j++) s += cpr[oi * 12 + j] * uf[j];
            xh[oi * 128 + pix] = s;
        }
    }
    __syncthreads();

    {
        float ufh[12];
#pragma unroll
        for (int ci = 0; ci < 4; ci++)
#pragma unroll
            for (int tap = 0; tap < 3; tap++) {
                float v = 0.f;
                int wc = cp + tap - 1;
                if ((unsigned)wc < (unsigned)WW)
                    v = xh[ci * 128 + pix + tap - 1];
                ufh[ci * 3 + tap] = v;
            }
        const float* cpr = &CsH[pix * 57];
        size_t obase = (size_t)(b * CC + gr * CGC) * PP + (size_t)h2 * 128 + pix;
#pragma unroll
        for (int oi = 0; oi < 4; oi++) {
            float s = cpr[48 + oi];
#pragma unroll
            for (int j = 0; j < 12; j++) s += cpr[oi * 12 + j] * ufh[j];
            size_t oidx = obase + (size_t)oi * PP;
            OUT[oidx] = s * ga1[gr * CGC + oi] + UF[oidx];
        }
    }
}

// ---------------- launch ----------------
extern "C" void kernel_launch(void* const* d_in, const int* in_sizes, int n_in,
                              void* d_out, int out_size) {
    const float* x       = (const float*)d_in[0];
    const float* dw1_w   = (const float*)d_in[1];
    const float* dw2_w   = (const float*)d_in[2];
    const float* proj_w  = (const float*)d_in[3];
    const float* lka0_w  = (const float*)d_in[4];
    const float* lkas_w  = (const float*)d_in[5];
    const float* lka1_w  = (const float*)d_in[6];
    const float* lka1_b  = (const float*)d_in[7];
    const float* sca_w   = (const float*)d_in[8];
    const float* sca_b   = (const float*)d_in[9];
    const float* c1a_w   = (const float*)d_in[10];
    const float* c1b_w   = (const float*)d_in[11];
    const float* c2a_w   = (const float*)d_in[12];
    const float* c2a_b   = (const float*)d_in[13];
    const float* c2b_w   = (const float*)d_in[14];
    const float* c2b_b   = (const float*)d_in[15];
    const float* c211_w  = (const float*)d_in[16];
    const float* c211_b  = (const float*)d_in[17];
    const float* w_cb    = (const float*)d_in[18];
    const float* b_cb    = (const float*)d_in[19];
    const float* attgam  = (const float*)d_in[20];
    const float* ga1     = (const float*)d_in[21];
    float* out = (float*)d_out;

    float *meanb, *scab, *ydw1, *yc1a, *attlin, *x1b, *ufb, *l1,
          *tg, *att, *x2b, *zb;
    cudaGetSymbolAddress((void**)&meanb, g_mean);
    cudaGetSymbolAddress((void**)&scab, g_sca);
    cudaGetSymbolAddress((void**)&ydw1, g_ydw1);
    cudaGetSymbolAddress((void**)&yc1a, g_yc1a);
    cudaGetSymbolAddress((void**)&attlin, g_attlin);
    cudaGetSymbolAddress((void**)&x1b, g_x1);
    cudaGetSymbolAddress((void**)&ufb, g_uf);
    cudaGetSymbolAddress((void**)&l1, g_l1);
    cudaGetSymbolAddress((void**)&tg, g_tg);
    cudaGetSymbolAddress((void**)&att, g_att);
    cudaGetSymbolAddress((void**)&x2b, g_x2);
    cudaGetSymbolAddress((void**)&zb, g_z);

    size_t gt_smem = GT_SMEM_FLOATS * sizeof(float);
    cudaFuncSetAttribute(gemm_tc<0>, cudaFuncAttributeMaxDynamicSharedMemorySize,
                         (int)gt_smem);
    cudaFuncSetAttribute(gemm_tc<1>, cudaFuncAttributeMaxDynamicSharedMemorySize,
                         (int)gt_smem);
    cudaFuncSetAttribute(gemm_tc<2>, cudaFuncAttributeMaxDynamicSharedMemorySize,
                         (int)gt_smem);

    // channel-attention branch
    meankern<<<BB * CC, 256>>>(x, meanb);
    scakern<<<BB, 256>>>(meanb, sca_w, sca_b, scab);

    // 1x1 convs from x, batched (dw1 -> ydw1, c1a -> yc1a, c211 -> attlin)
    gemm_tc<0><<<dim3(32, 10, BB), 256, gt_smem>>>(
        dw1_w, c1a_w, c211_w, c211_b, x, ydw1, yc1a, attlin,
        nullptr, nullptr, nullptr);

    // depthwise: two 3x3 merged; LKA chain separate (padded tiles, no predicates)
    dw3x3_pair<<<BB * CC * 2, 256>>>(ydw1, dw2_w, x1b, yc1a, c1b_w, ufb);
    lka_chain<<<BB * CC, 256>>>(x, lka0_w, lkas_w, l1);

    // attention map
    c2a_gate<<<dim3(BB * 16, 8), 256>>>(x, c2a_w, c2a_b, tg);
    att_mix<<<dim3(NSET, 4, BB), 256>>>(tg, c2b_w, c2b_b, attgam, attlin, att);

    // dual-pass IKBA (k-chunked, 3 CTA/SM)
    size_t shmem = IKBA_SMEM_FLOATS * sizeof(float);
    cudaFuncSetAttribute(ikba_dual, cudaFuncAttributeMaxDynamicSharedMemorySize,
                         (int)shmem);
    ikba_dual<<<dim3(GG, 32, BB), 128, shmem>>>(att, w_cb, b_cb, ga1, ufb, x2b);

    // lka1 GEMM with fused elementwise merge: z = (W@l1+b)*x1*x2*sca
    gemm_tc<1><<<dim3(32, 4, BB), 256, gt_smem>>>(
        lka1_w, nullptr, nullptr, lka1_b, l1, zb, nullptr, nullptr,
        x1b, x2b, scab);

    // final projection
    gemm_tc<2><<<dim3(32, 4, BB), 256, gt_smem>>>(
        proj_w, nullptr, nullptr, nullptr, zb, out, nullptr, nullptr,
        nullptr, nullptr, nullptr);
}